// round 12
// baseline (speedup 1.0000x reference)
#include <cuda_runtime.h>
#include <cuda_bf16.h>
#include <math.h>
#include <stdint.h>

#define Bb  2
#define Tt  10
#define Nn  1024
#define Dd  1024
#define NHh 16
#define HDd 64
#define BT  (Bb*Tt)

// ---------------- scratch (static device globals; no allocation) ----------------
__device__ float g_traj[(size_t)Nn * Nn];

// bf16 hi/lo operand pairs
__device__ __nv_bfloat16 g_dh[(size_t)Bb * Nn * Dd],  g_dl[(size_t)Bb * Nn * Dd];
__device__ __nv_bfloat16 g_w3h[(size_t)3 * Dd * Dd],  g_w3l[(size_t)3 * Dd * Dd];
__device__ __nv_bfloat16 g_woh[(size_t)Dd * Dd],      g_wol[(size_t)Dd * Dd];
__device__ __nv_bfloat16 g_qh[(size_t)Bb * Nn * Dd],  g_ql[(size_t)Bb * Nn * Dd];   // Q/8
__device__ __nv_bfloat16 g_kh[(size_t)Bb * Nn * Dd],  g_kl[(size_t)Bb * Nn * Dd];
__device__ __nv_bfloat16 g_vh[(size_t)Bb * Nn * Dd],  g_vl[(size_t)Bb * Nn * Dd];
__device__ __nv_bfloat16 g_aoh[(size_t)Bb * Nn * Dd], g_aol[(size_t)Bb * Nn * Dd];
// unnormalized exp(scores) hi part (for entropy) + per-row 1/rowsum
__device__ __nv_bfloat16 g_eh[(size_t)Bb * NHh * Nn * Nn];
__device__ float g_invs[(size_t)Bb * NHh * Nn];
// split-K fp32 partials: qkv uses slots 0..5 (mat*2+kh), out reuses slots 0..1
__device__ float g_part[(size_t)6 * Bb * Nn * Dd];

// ================= HMMA helpers =================
__device__ __forceinline__ uint32_t smem_to_u32(const void* p) {
    uint32_t a;
    asm("{ .reg .u64 t; cvta.to.shared.u64 t, %1; cvt.u32.u64 %0, t; }" : "=r"(a) : "l"(p));
    return a;
}
__device__ __forceinline__ void cp16(uint32_t dst, const void* src) {
    asm volatile("cp.async.cg.shared.global [%0], [%1], 16;" :: "r"(dst), "l"(src));
}
#define CP_COMMIT() asm volatile("cp.async.commit_group;" ::: "memory")
#define CP_WAIT0()  asm volatile("cp.async.wait_group 0;" ::: "memory")

__device__ __forceinline__ void ldsm_x4(uint32_t* r, uint32_t addr) {
    asm volatile("ldmatrix.sync.aligned.m8n8.x4.shared.b16 {%0,%1,%2,%3}, [%4];"
                 : "=r"(r[0]), "=r"(r[1]), "=r"(r[2]), "=r"(r[3]) : "r"(addr));
}
__device__ __forceinline__ void ldsm_x4_t(uint32_t* r, uint32_t addr) {
    asm volatile("ldmatrix.sync.aligned.m8n8.x4.trans.shared.b16 {%0,%1,%2,%3}, [%4];"
                 : "=r"(r[0]), "=r"(r[1]), "=r"(r[2]), "=r"(r[3]) : "r"(addr));
}
// NON-volatile: lets ptxas interleave independent acc chains to hide HMMA latency.
__device__ __forceinline__ void mma_bf16(float* c, const uint32_t* a, uint32_t b0, uint32_t b1) {
    asm("mma.sync.aligned.m16n8k16.row.col.f32.bf16.bf16.f32 "
        "{%0,%1,%2,%3}, {%4,%5,%6,%7}, {%8,%9}, {%0,%1,%2,%3};"
        : "+f"(c[0]), "+f"(c[1]), "+f"(c[2]), "+f"(c[3])
        : "r"(a[0]), "r"(a[1]), "r"(a[2]), "r"(a[3]), "r"(b0), "r"(b1));
}
__device__ __forceinline__ __nv_bfloat162 split_hi2(float a, float b, float* ra, float* rb) {
    __nv_bfloat16 h0 = __float2bfloat16_rn(a), h1 = __float2bfloat16_rn(b);
    *ra = a - __bfloat162float(h0);
    *rb = b - __bfloat162float(h1);
    return __nv_bfloat162(h0, h1);
}
__device__ __forceinline__ uint32_t pack_bf162(__nv_bfloat16 a, __nv_bfloat16 b) {
    __nv_bfloat162 p(a, b);
    return *(uint32_t*)&p;
}

// ---------------- block reduction (256 threads) ----------------
__device__ __forceinline__ float blk_sum(float v) {
    __shared__ float red[8];
    #pragma unroll
    for (int o = 16; o > 0; o >>= 1) v += __shfl_xor_sync(0xffffffffu, v, o);
    int w = threadIdx.x >> 5, l = threadIdx.x & 31;
    if (l == 0) red[w] = v;
    __syncthreads();
    if (w == 0) {
        float r = (l < 8) ? red[l] : 0.0f;
        #pragma unroll
        for (int o = 4; o > 0; o >>= 1) r += __shfl_xor_sync(0xffffffffu, r, o);
        if (l == 0) red[0] = r;
    }
    __syncthreads();
    float out = red[0];
    __syncthreads();
    return out;
}

// ---------------- fp32 -> bf16 hi/lo splits ----------------
__global__ __launch_bounds__(256) void split_data(const float* __restrict__ s) {
    int i = blockIdx.x * 256 + threadIdx.x;
    float4 x = ((const float4*)s)[i];
    float r0, r1, r2, r3;
    __nv_bfloat162 h01 = split_hi2(x.x, x.y, &r0, &r1);
    __nv_bfloat162 h23 = split_hi2(x.z, x.w, &r2, &r3);
    ((__nv_bfloat162*)g_dh)[i * 2 + 0] = h01;
    ((__nv_bfloat162*)g_dh)[i * 2 + 1] = h23;
    ((__nv_bfloat162*)g_dl)[i * 2 + 0] = __nv_bfloat162(__float2bfloat16_rn(r0), __float2bfloat16_rn(r1));
    ((__nv_bfloat162*)g_dl)[i * 2 + 1] = __nv_bfloat162(__float2bfloat16_rn(r2), __float2bfloat16_rn(r3));
}

__global__ __launch_bounds__(256) void split_w(const float* __restrict__ Wq, const float* __restrict__ Wk,
                                               const float* __restrict__ Wv, const float* __restrict__ Wo) {
    int blk = blockIdx.x;
    int m = blk >> 10;
    const float* src = (m == 0) ? Wq : (m == 1) ? Wk : (m == 2) ? Wv : Wo;
    __nv_bfloat16* hi = (m < 3) ? g_w3h + (size_t)m * 1048576 : g_woh;
    __nv_bfloat16* lo = (m < 3) ? g_w3l + (size_t)m * 1048576 : g_wol;
    int i = (blk & 1023) * 256 + threadIdx.x;
    float4 x = ((const float4*)src)[i];
    float r0, r1, r2, r3;
    __nv_bfloat162 h01 = split_hi2(x.x, x.y, &r0, &r1);
    __nv_bfloat162 h23 = split_hi2(x.z, x.w, &r2, &r3);
    ((__nv_bfloat162*)hi)[i * 2 + 0] = h01;
    ((__nv_bfloat162*)hi)[i * 2 + 1] = h23;
    ((__nv_bfloat162*)lo)[i * 2 + 0] = __nv_bfloat162(__float2bfloat16_rn(r0), __float2bfloat16_rn(r1));
    ((__nv_bfloat162*)lo)[i * 2 + 1] = __nv_bfloat162(__float2bfloat16_rn(r2), __float2bfloat16_rn(r3));
}

// ================= HMMA GEMM core: 128x128 tile, K-chunk 32, 2-stage, SPLIT-K =================
// Identical inner loop to round-11 winner; K range [k0, k0+512), raw fp32 partials out.
#define GSTG       40960
#define GMAT       10240
#define GEMM_SMEM  (2 * GSTG)

__device__ __forceinline__ void hmma_gemm_body(const __nv_bfloat16* __restrict__ Ah,
                                               const __nv_bfloat16* __restrict__ Al,
                                               const __nv_bfloat16* __restrict__ Wh,
                                               const __nv_bfloat16* __restrict__ Wl,
                                               int k0, float* __restrict__ Cpart) {
    extern __shared__ __align__(16) char gsm[];
    uint32_t ub = smem_to_u32(gsm);
    int tid = threadIdx.x, lane = tid & 31, wid = tid >> 5;
    int wm = wid & 3, wn = wid >> 2;
    int m0 = blockIdx.y << 7, n0 = blockIdx.x << 7;

    const __nv_bfloat16* srcs[4] = {
        Ah + (size_t)m0 * Dd + k0, Al + (size_t)m0 * Dd + k0,
        Wh + (size_t)n0 * Dd + k0, Wl + (size_t)n0 * Dd + k0 };

    float acc[2][8][4];
    #pragma unroll
    for (int i = 0; i < 2; i++)
        #pragma unroll
        for (int j = 0; j < 8; j++)
            #pragma unroll
            for (int k = 0; k < 4; k++) acc[i][j][k] = 0.0f;

    // per-thread cp slots: 2048 cp16/stage -> 8 per thread
    #pragma unroll
    for (int s = 0; s < 8; s++) {
        int idx = tid + (s << 8);
        int mat = idx >> 9, row = (idx >> 2) & 127, seg = idx & 3;
        cp16(ub + mat * GMAT + row * 80 + seg * 16,
             srcs[mat] + (size_t)row * Dd + seg * 8);
    }
    CP_COMMIT();

    int rsel = lane & 15;
    int cselb = ((lane >> 4) << 4);   // 0 or 16

    for (int c = 0; c < 16; c++) {
        int st = c & 1;
        CP_WAIT0();
        __syncthreads();
        if (c + 1 < 16) {
            int nst = st ^ 1, kc = (c + 1) << 5;
            #pragma unroll
            for (int s = 0; s < 8; s++) {
                int idx = tid + (s << 8);
                int mat = idx >> 9, row = (idx >> 2) & 127, seg = idx & 3;
                cp16(ub + nst * GSTG + mat * GMAT + row * 80 + seg * 16,
                     srcs[mat] + (size_t)row * Dd + kc + seg * 8);
            }
            CP_COMMIT();
        }

        uint32_t base = ub + st * GSTG;
        #pragma unroll
        for (int kk = 0; kk < 2; kk++) {
            uint32_t ah[2][4], al[2][4];
            #pragma unroll
            for (int mb = 0; mb < 2; mb++) {
                int row = wm * 32 + mb * 16 + rsel;
                ldsm_x4(ah[mb], base + row * 80 + kk * 32 + cselb);
                ldsm_x4(al[mb], base + GMAT + row * 80 + kk * 32 + cselb);
            }
            #pragma unroll
            for (int np = 0; np < 4; np++) {
                uint32_t bh[4], bl[4];
                int row = wn * 64 + np * 16 + rsel;
                ldsm_x4(bh, base + 2 * GMAT + row * 80 + kk * 32 + cselb);
                ldsm_x4(bl, base + 3 * GMAT + row * 80 + kk * 32 + cselb);
                #pragma unroll
                for (int mb = 0; mb < 2; mb++) {
                    mma_bf16(acc[mb][2 * np + 0], ah[mb], bh[0], bh[2]);
                    mma_bf16(acc[mb][2 * np + 1], ah[mb], bh[1], bh[3]);
                    mma_bf16(acc[mb][2 * np + 0], ah[mb], bl[0], bl[2]);
                    mma_bf16(acc[mb][2 * np + 1], ah[mb], bl[1], bl[3]);
                    mma_bf16(acc[mb][2 * np + 0], al[mb], bh[0], bh[2]);
                    mma_bf16(acc[mb][2 * np + 1], al[mb], bh[1], bh[3]);
                }
            }
        }
    }

    // epilogue: raw fp32 partials (bias/scale/split deferred to reduce kernel)
    #pragma unroll
    for (int mb = 0; mb < 2; mb++) {
        int r0 = m0 + wm * 32 + mb * 16 + (lane >> 2);
        #pragma unroll
        for (int nb = 0; nb < 8; nb++) {
            int col = n0 + wn * 64 + nb * 8 + ((lane & 3) << 1);
            *(float2*)(Cpart + (size_t)r0 * Dd + col)       = make_float2(acc[mb][nb][0], acc[mb][nb][1]);
            *(float2*)(Cpart + (size_t)(r0 + 8) * Dd + col) = make_float2(acc[mb][nb][2], acc[mb][nb][3]);
        }
    }
}

// qkv split-K: grid.z = 6, mat = z>>1, kh = z&1
__global__ __launch_bounds__(256, 2) void qkv_tc() {
    int z = blockIdx.z;
    int mat = z >> 1, kh = z & 1;
    const __nv_bfloat16* Wh = g_w3h + (size_t)mat * 1048576;
    const __nv_bfloat16* Wl = g_w3l + (size_t)mat * 1048576;
    float* Cpart = g_part + (size_t)z * 2097152;
    hmma_gemm_body(g_dh, g_dl, Wh, Wl, kh * 512, Cpart);
}

// out split-K: grid.z = 2 (kh)
__global__ __launch_bounds__(256, 2) void out_tc() {
    int kh = blockIdx.z;
    float* Cpart = g_part + (size_t)kh * 2097152;
    hmma_gemm_body(g_aoh, g_aol, g_woh, g_wol, kh * 512, Cpart);
}

// ---------------- split-K reduce: partials -> bias/scale -> bf16 hi/lo ----------------
__global__ __launch_bounds__(256) void reduce_qkv(const float* __restrict__ bq,
                                                  const float* __restrict__ bk,
                                                  const float* __restrict__ bv) {
    size_t p = (size_t)blockIdx.x * 256 + threadIdx.x;   // float4 index; 3*524288 total
    int mat = (int)(p >> 19);
    size_t r4 = p & 524287;
    const float4* P = (const float4*)g_part;
    float4 a = P[(size_t)(mat * 2 + 0) * 524288 + r4];
    float4 b = P[(size_t)(mat * 2 + 1) * 524288 + r4];
    const float* bias = (mat == 0) ? bq : (mat == 1) ? bk : bv;
    float4 bi = *(const float4*)(bias + ((r4 & 255) << 2));
    float scale = (mat == 0) ? 0.125f : 1.0f;
    float x0 = (a.x + b.x + bi.x) * scale, x1 = (a.y + b.y + bi.y) * scale;
    float x2 = (a.z + b.z + bi.z) * scale, x3 = (a.w + b.w + bi.w) * scale;
    __nv_bfloat16* hi = (mat == 0) ? g_qh : (mat == 1) ? g_kh : g_vh;
    __nv_bfloat16* lo = (mat == 0) ? g_ql : (mat == 1) ? g_kl : g_vl;
    float l0, l1, l2, l3;
    __nv_bfloat162 h01 = split_hi2(x0, x1, &l0, &l1);
    __nv_bfloat162 h23 = split_hi2(x2, x3, &l2, &l3);
    ((__nv_bfloat162*)hi)[r4 * 2 + 0] = h01;
    ((__nv_bfloat162*)hi)[r4 * 2 + 1] = h23;
    ((__nv_bfloat162*)lo)[r4 * 2 + 0] = __nv_bfloat162(__float2bfloat16_rn(l0), __float2bfloat16_rn(l1));
    ((__nv_bfloat162*)lo)[r4 * 2 + 1] = __nv_bfloat162(__float2bfloat16_rn(l2), __float2bfloat16_rn(l3));
}

__global__ __launch_bounds__(256) void reduce_out(const float* __restrict__ bo,
                                                  float* __restrict__ out) {
    size_t p = (size_t)blockIdx.x * 256 + threadIdx.x;   // 524288 float4 total
    const float4* P = (const float4*)g_part;
    float4 a = P[p];
    float4 b = P[524288 + p];
    float4 bi = *(const float4*)(bo + ((p & 255) << 2));
    ((float4*)out)[p] = make_float4(a.x + b.x + bi.x, a.y + b.y + bi.y,
                                    a.z + b.z + bi.z, a.w + b.w + bi.w);
}

// ================= fused attention: scores+traj -> exp -> PV, flash-style =================
#define AQH 0
#define AQL 9216
#define ASTG(st) (18432 + (st) * 18432)
#define ARS 55296
#define AIV 55808
#define ATTN_SMEM 56064

__global__ __launch_bounds__(256, 2) void attn_fused() {
    extern __shared__ __align__(16) char sm[];
    uint32_t ub = smem_to_u32(sm);
    int tid = threadIdx.x, lane = tid & 31, wid = tid >> 5;
    int wm = wid & 3, wn = wid >> 2;
    int g = lane >> 2, t = lane & 3;
    int rsel = lane & 15, csel = (lane >> 4) << 3;
    int bh = blockIdx.y, b = bh >> 4, h = bh & 15;
    int i0 = blockIdx.x << 6;

    const __nv_bfloat16* kvsrc[4] = { g_kh, g_kl, g_vh, g_vl };
    #pragma unroll
    for (int s = 0; s < 4; s++) {
        int idx = tid + (s << 8);
        int mat = idx >> 9, row = (idx >> 3) & 63, seg = idx & 7;
        const __nv_bfloat16* src = (mat == 0 ? g_qh : g_ql) +
            ((size_t)(b * Nn + i0 + row)) * Dd + h * HDd + seg * 8;
        cp16(ub + (mat ? AQL : AQH) + (row * 72 + seg * 8) * 2, src);
    }
    #pragma unroll
    for (int s = 0; s < 4; s++) {
        int idx = tid + (s << 8);
        int mat = idx >> 8, row = (idx >> 3) & 31, seg = idx & 7;
        const __nv_bfloat16* src = kvsrc[mat] + ((size_t)(b * Nn + row)) * Dd + h * HDd + seg * 8;
        cp16(ub + ASTG(0) + mat * 4608 + (row * 72 + seg * 8) * 2, src);
    }
    CP_COMMIT();

    float pacc[8][4];
    #pragma unroll
    for (int i = 0; i < 8; i++)
        #pragma unroll
        for (int j = 0; j < 4; j++) pacc[i][j] = 0.0f;
    float rs0 = 0.0f, rs1 = 0.0f;

    int i_r0 = i0 + wm * 16 + g;

    for (int c = 0; c < 32; c++) {
        int st = c & 1;
        CP_WAIT0();
        __syncthreads();
        if (c < 31) {
            int jc1 = (c + 1) << 5, nst = st ^ 1;
            #pragma unroll
            for (int s = 0; s < 4; s++) {
                int idx = tid + (s << 8);
                int mat = idx >> 8, row = (idx >> 3) & 31, seg = idx & 7;
                const __nv_bfloat16* src = kvsrc[mat] +
                    ((size_t)(b * Nn + jc1 + row)) * Dd + h * HDd + seg * 8;
                cp16(ub + ASTG(nst) + mat * 4608 + (row * 72 + seg * 8) * 2, src);
            }
            CP_COMMIT();
        }

        uint32_t kbase = ub + ASTG(st);
        int jc = c << 5;

        float sacc0[4] = {0.f, 0.f, 0.f, 0.f};
        float sacc1[4] = {0.f, 0.f, 0.f, 0.f};
        #pragma unroll
        for (int k = 0; k < 4; k++) {
            uint32_t qh[4], ql[4], kh[4], kl[4];
            uint32_t qaddr = (uint32_t)(((wm * 16 + rsel) * 72 + k * 16 + csel) * 2);
            uint32_t kaddr = (uint32_t)(((wn * 16 + rsel) * 72 + k * 16 + csel) * 2);
            ldsm_x4(qh, ub + AQH + qaddr);
            ldsm_x4(ql, ub + AQL + qaddr);
            ldsm_x4(kh, kbase + kaddr);
            ldsm_x4(kl, kbase + 4608 + kaddr);
            mma_bf16(sacc0, qh, kh[0], kh[2]); mma_bf16(sacc1, qh, kh[1], kh[3]);
            mma_bf16(sacc0, qh, kl[0], kl[2]); mma_bf16(sacc1, qh, kl[1], kl[3]);
            mma_bf16(sacc0, ql, kh[0], kh[2]); mma_bf16(sacc1, ql, kh[1], kh[3]);
        }

        uint32_t ah[4], al[4];
        {
            float* sa = sacc0;
            #pragma unroll
            for (int nt = 0; nt < 2; nt++) {
                int jj = jc + wn * 16 + nt * 8 + 2 * t;
                float2 tv0 = *(const float2*)(g_traj + (size_t)i_r0 * Nn + jj);
                float2 tv1 = *(const float2*)(g_traj + (size_t)(i_r0 + 8) * Nn + jj);
                float e0 = __expf(sa[0] + tv0.x), e1 = __expf(sa[1] + tv0.y);
                float e2 = __expf(sa[2] + tv1.x), e3 = __expf(sa[3] + tv1.y);
                rs0 += e0 + e1; rs1 += e2 + e3;
                __nv_bfloat16 h0 = __float2bfloat16_rn(e0), h1 = __float2bfloat16_rn(e1);
                __nv_bfloat16 h2 = __float2bfloat16_rn(e2), h3 = __float2bfloat16_rn(e3);
                float l0 = e0 - __bfloat162float(h0), l1 = e1 - __bfloat162float(h1);
                float l2 = e2 - __bfloat162float(h2), l3 = e3 - __bfloat162float(h3);
                *(__nv_bfloat162*)(g_eh + ((size_t)bh * Nn + i_r0) * Nn + jj)     = __nv_bfloat162(h0, h1);
                *(__nv_bfloat162*)(g_eh + ((size_t)bh * Nn + i_r0 + 8) * Nn + jj) = __nv_bfloat162(h2, h3);
                ah[nt * 2 + 0] = pack_bf162(h0, h1);
                ah[nt * 2 + 1] = pack_bf162(h2, h3);
                al[nt * 2 + 0] = pack_bf162(__float2bfloat16_rn(l0), __float2bfloat16_rn(l1));
                al[nt * 2 + 1] = pack_bf162(__float2bfloat16_rn(l2), __float2bfloat16_rn(l3));
                sa = sacc1;
            }
        }

        #pragma unroll
        for (int db = 0; db < 4; db++) {
            uint32_t vh[4], vl[4];
            uint32_t vaddr = (uint32_t)(((wn * 16 + rsel) * 72 + db * 16 + csel) * 2);
            ldsm_x4_t(vh, kbase + 9216 + vaddr);
            ldsm_x4_t(vl, kbase + 13824 + vaddr);
            mma_bf16(pacc[2 * db + 0], ah, vh[0], vh[1]); mma_bf16(pacc[2 * db + 1], ah, vh[2], vh[3]);
            mma_bf16(pacc[2 * db + 0], al, vh[0], vh[1]); mma_bf16(pacc[2 * db + 1], al, vh[2], vh[3]);
            mma_bf16(pacc[2 * db + 0], ah, vl[0], vl[1]); mma_bf16(pacc[2 * db + 1], ah, vl[2], vl[3]);
        }
    }

    rs0 += __shfl_xor_sync(0xffffffffu, rs0, 1);
    rs0 += __shfl_xor_sync(0xffffffffu, rs0, 2);
    rs1 += __shfl_xor_sync(0xffffffffu, rs1, 1);
    rs1 += __shfl_xor_sync(0xffffffffu, rs1, 2);
    float* s_rs = (float*)(sm + ARS);
    float* s_iv = (float*)(sm + AIV);
    if (t == 0) {
        s_rs[wn * 64 + wm * 16 + g]     = rs0;
        s_rs[wn * 64 + wm * 16 + g + 8] = rs1;
    }
    __syncthreads();
    if (tid < 64) {
        float s = s_rs[tid] + s_rs[64 + tid];
        float inv = 1.0f / s;
        s_iv[tid] = inv;
        g_invs[(size_t)bh * Nn + i0 + tid] = inv;
    }
    __syncthreads();

    float* red = (float*)(sm + ASTG(0)) + wm * 1056;
    if (wn == 0) {
        #pragma unroll
        for (int nt = 0; nt < 8; nt++) {
            int col = nt * 8 + 2 * t;
            red[g * 66 + col]           = pacc[nt][0];
            red[g * 66 + col + 1]       = pacc[nt][1];
            red[(g + 8) * 66 + col]     = pacc[nt][2];
            red[(g + 8) * 66 + col + 1] = pacc[nt][3];
        }
    }
    __syncthreads();
    if (wn == 1) {
        float inv0 = s_iv[wm * 16 + g], inv1 = s_iv[wm * 16 + g + 8];
        #pragma unroll
        for (int nt = 0; nt < 8; nt++) {
            int col = nt * 8 + 2 * t;
            float x0 = (pacc[nt][0] + red[g * 66 + col])           * inv0;
            float x1 = (pacc[nt][1] + red[g * 66 + col + 1])       * inv0;
            float x2 = (pacc[nt][2] + red[(g + 8) * 66 + col])     * inv1;
            float x3 = (pacc[nt][3] + red[(g + 8) * 66 + col + 1]) * inv1;
            float l0, l1, l2, l3;
            __nv_bfloat162 h01 = split_hi2(x0, x1, &l0, &l1);
            __nv_bfloat162 h23 = split_hi2(x2, x3, &l2, &l3);
            size_t o0 = ((size_t)b * Nn + i_r0) * Dd + h * HDd + col;
            size_t o1 = ((size_t)b * Nn + i_r0 + 8) * Dd + h * HDd + col;
            *(__nv_bfloat162*)(g_aoh + o0) = h01;
            *(__nv_bfloat162*)(g_aoh + o1) = h23;
            *(__nv_bfloat162*)(g_aol + o0) = __nv_bfloat162(__float2bfloat16_rn(l0), __float2bfloat16_rn(l1));
            *(__nv_bfloat162*)(g_aol + o1) = __nv_bfloat162(__float2bfloat16_rn(l2), __float2bfloat16_rn(l3));
        }
    }
}

// ---------------- entropy + certainty ----------------
__global__ __launch_bounds__(256) void entropy_kernel(const float* __restrict__ cert,
                                                      float* __restrict__ out_cert) {
    int bi = blockIdx.x;
    int b = bi >> 10, i = bi & 1023;
    int tid = threadIdx.x;

    float a0 = 0.f, a1 = 0.f, a2 = 0.f, a3 = 0.f;
    #pragma unroll
    for (int hh = 0; hh < NHh; hh++) {
        int bh = b * NHh + hh;
        float inv = g_invs[(size_t)bh * Nn + i];
        const __nv_bfloat162* row = (const __nv_bfloat162*)(g_eh + ((size_t)bh * Nn + i) * Nn);
        __nv_bfloat162 v0 = row[tid * 2], v1 = row[tid * 2 + 1];
        a0 += __bfloat162float(v0.x) * inv;
        a1 += __bfloat162float(v0.y) * inv;
        a2 += __bfloat162float(v1.x) * inv;
        a3 += __bfloat162float(v1.y) * inv;
    }
    a0 *= (1.0f / NHh); a1 *= (1.0f / NHh); a2 *= (1.0f / NHh); a3 *= (1.0f / NHh);
    float hl = 0.0f;
    a0 = fmaxf(a0, 1e-10f); hl -= a0 * __logf(a0);
    a1 = fmaxf(a1, 1e-10f); hl -= a1 * __logf(a1);
    a2 = fmaxf(a2, 1e-10f); hl -= a2 * __logf(a2);
    a3 = fmaxf(a3, 1e-10f); hl -= a3 * __logf(a3);
    float H = blk_sum(hl);
    if (tid == 0) {
        float sig = 1.0f / (1.0f + __expf(H - 6.9314718055994531f));
        out_cert[bi] = fmaxf(cert[bi], sig);
    }
}

// ---------------- trajectory pairwise similarity ----------------
__device__ __forceinline__ float fast_sqrt(float x) {
    return x * rsqrtf(x + 1e-30f);
}

__global__ __launch_bounds__(1024) void traj_kernel(const float* __restrict__ pos,
                                                    const float* __restrict__ quat) {
    __shared__ float Pi[3][BT][32], Pj[3][BT][32];
    __shared__ float Qi[4][BT][32], Qj[4][BT][32];
    int i0 = blockIdx.y * 32, j0 = blockIdx.x * 32;
    int tid = threadIdx.y * 32 + threadIdx.x;

    for (int idx = tid; idx < BT * 32; idx += 1024) {
        int bt = idx >> 5, r = idx & 31;
        size_t pi = ((size_t)bt * Nn + i0 + r) * 3;
        size_t pj = ((size_t)bt * Nn + j0 + r) * 3;
        Pi[0][bt][r] = pos[pi + 0]; Pi[1][bt][r] = pos[pi + 1]; Pi[2][bt][r] = pos[pi + 2];
        Pj[0][bt][r] = pos[pj + 0]; Pj[1][bt][r] = pos[pj + 1]; Pj[2][bt][r] = pos[pj + 2];
        size_t qi = ((size_t)bt * Nn + i0 + r) * 4;
        size_t qj = ((size_t)bt * Nn + j0 + r) * 4;
        Qi[0][bt][r] = quat[qi + 0]; Qi[1][bt][r] = quat[qi + 1];
        Qi[2][bt][r] = quat[qi + 2]; Qi[3][bt][r] = quat[qi + 3];
        Qj[0][bt][r] = quat[qj + 0]; Qj[1][bt][r] = quat[qj + 1];
        Qj[2][bt][r] = quat[qj + 2]; Qj[3][bt][r] = quat[qj + 3];
    }
    __syncthreads();

    int ti = threadIdx.y, tj = threadIdx.x;
    float spd = 0.0f, sqm = 0.0f, sqp = 0.0f;
    #pragma unroll
    for (int bt = 0; bt < BT; bt++) {
        float dx = Pi[0][bt][ti] - Pj[0][bt][tj];
        float dy = Pi[1][bt][ti] - Pj[1][bt][tj];
        float dz = Pi[2][bt][ti] - Pj[2][bt][tj];
        spd += fast_sqrt(dx * dx + dy * dy + dz * dz);
        float a0 = Qi[0][bt][ti], a1 = Qi[1][bt][ti], a2 = Qi[2][bt][ti], a3 = Qi[3][bt][ti];
        float b0 = Qj[0][bt][tj], b1 = Qj[1][bt][tj], b2 = Qj[2][bt][tj], b3 = Qj[3][bt][tj];
        float m0 = a0 - b0, m1 = a1 - b1, m2 = a2 - b2, m3 = a3 - b3;
        float p0 = a0 + b0, p1 = a1 + b1, p2 = a2 + b2, p3 = a3 + b3;
        sqm += fast_sqrt(m0 * m0 + m1 * m1 + m2 * m2 + m3 * m3);
        sqp += fast_sqrt(p0 * p0 + p1 * p1 + p2 * p2 + p3 * p3);
    }
    float pd = spd * (1.0f / BT);
    float qd = fminf(sqm, sqp) * (1.0f / BT);
    g_traj[(size_t)(i0 + ti) * Nn + (j0 + tj)] = __expf(-(pd + qd));
}

// ---------------- row-normalize traj (folds in 0.5 bias scale) ----------------
__global__ __launch_bounds__(256) void traj_norm_kernel() {
    float* row = g_traj + (size_t)blockIdx.x * Nn;
    float4 v = ((const float4*)row)[threadIdx.x];
    float s = blk_sum(v.x + v.y + v.z + v.w);
    float sc = 0.5f / s;
    v.x *= sc; v.y *= sc; v.z *= sc; v.w *= sc;
    ((float4*)row)[threadIdx.x] = v;
}

// ---------------- launch ----------------
extern "C" void kernel_launch(void* const* d_in, const int* in_sizes, int n_in,
                              void* d_out, int out_size) {
    const float* data  = (const float*)d_in[0];
    const float* tpos  = (const float*)d_in[1];
    const float* tquat = (const float*)d_in[2];
    const float* cert  = (const float*)d_in[3];
    const float* bq = (const float*)d_in[5];
    const float* bk = (const float*)d_in[7];
    const float* bv = (const float*)d_in[9];
    const float* Wq = (const float*)d_in[4];
    const float* Wk = (const float*)d_in[6];
    const float* Wv = (const float*)d_in[8];
    const float* Wo = (const float*)d_in[10];
    const float* bo = (const float*)d_in[11];
    float* out = (float*)d_out;

    // idempotent, host-side, capture-safe (no enqueue, no allocation)
    cudaFuncSetAttribute(attn_fused, cudaFuncAttributeMaxDynamicSharedMemorySize, ATTN_SMEM);
    cudaFuncSetAttribute(qkv_tc, cudaFuncAttributeMaxDynamicSharedMemorySize, GEMM_SMEM);
    cudaFuncSetAttribute(out_tc, cudaFuncAttributeMaxDynamicSharedMemorySize, GEMM_SMEM);

    split_data<<<2048, 256>>>(data);
    split_w<<<4096, 256>>>(Wq, Wk, Wv, Wo);
    traj_kernel<<<dim3(32, 32), dim3(32, 32)>>>(tpos, tquat);
    qkv_tc<<<dim3(8, 16, 6), 256, GEMM_SMEM>>>();          // slot 4: ncu captures this
    reduce_qkv<<<6144, 256>>>(bq, bk, bv);
    traj_norm_kernel<<<Nn, 256>>>();
    attn_fused<<<dim3(16, 32), 256, ATTN_SMEM>>>();
    entropy_kernel<<<Bb * Nn, 256>>>(cert, out + (size_t)Bb * Nn * Dd);
    out_tc<<<dim3(8, 16, 2), 256, GEMM_SMEM>>>();
    reduce_out<<<2048, 256>>>(bo, out);
}

// round 13
// speedup vs baseline: 1.0028x; 1.0028x over previous
#include <cuda_runtime.h>
#include <cuda_bf16.h>
#include <math.h>
#include <stdint.h>

#define Bb  2
#define Tt  10
#define Nn  1024
#define Dd  1024
#define NHh 16
#define HDd 64
#define BT  (Bb*Tt)

// ---------------- scratch (static device globals; no allocation) ----------------
__device__ float g_traj[(size_t)Nn * Nn];

// bf16 hi/lo operand pairs
__device__ __nv_bfloat16 g_dh[(size_t)Bb * Nn * Dd],  g_dl[(size_t)Bb * Nn * Dd];
__device__ __nv_bfloat16 g_w3h[(size_t)3 * Dd * Dd],  g_w3l[(size_t)3 * Dd * Dd];
__device__ __nv_bfloat16 g_woh[(size_t)Dd * Dd],      g_wol[(size_t)Dd * Dd];
__device__ __nv_bfloat16 g_qh[(size_t)Bb * Nn * Dd],  g_ql[(size_t)Bb * Nn * Dd];   // Q/8
__device__ __nv_bfloat16 g_kh[(size_t)Bb * Nn * Dd],  g_kl[(size_t)Bb * Nn * Dd];
__device__ __nv_bfloat16 g_vh[(size_t)Bb * Nn * Dd],  g_vl[(size_t)Bb * Nn * Dd];
__device__ __nv_bfloat16 g_aoh[(size_t)Bb * Nn * Dd], g_aol[(size_t)Bb * Nn * Dd];
// unnormalized exp(scores) hi part (for entropy) + per-row 1/rowsum
__device__ __nv_bfloat16 g_eh[(size_t)Bb * NHh * Nn * Nn];
__device__ float g_invs[(size_t)Bb * NHh * Nn];
// split-K fp32 partials (out projection only)
__device__ float g_part[(size_t)2 * Bb * Nn * Dd];

// ================= HMMA helpers =================
__device__ __forceinline__ uint32_t smem_to_u32(const void* p) {
    uint32_t a;
    asm("{ .reg .u64 t; cvta.to.shared.u64 t, %1; cvt.u32.u64 %0, t; }" : "=r"(a) : "l"(p));
    return a;
}
__device__ __forceinline__ void cp16(uint32_t dst, const void* src) {
    asm volatile("cp.async.cg.shared.global [%0], [%1], 16;" :: "r"(dst), "l"(src));
}
#define CP_COMMIT() asm volatile("cp.async.commit_group;" ::: "memory")
#define CP_WAIT0()  asm volatile("cp.async.wait_group 0;" ::: "memory")

__device__ __forceinline__ void ldsm_x4(uint32_t* r, uint32_t addr) {
    asm volatile("ldmatrix.sync.aligned.m8n8.x4.shared.b16 {%0,%1,%2,%3}, [%4];"
                 : "=r"(r[0]), "=r"(r[1]), "=r"(r[2]), "=r"(r[3]) : "r"(addr));
}
__device__ __forceinline__ void ldsm_x4_t(uint32_t* r, uint32_t addr) {
    asm volatile("ldmatrix.sync.aligned.m8n8.x4.trans.shared.b16 {%0,%1,%2,%3}, [%4];"
                 : "=r"(r[0]), "=r"(r[1]), "=r"(r[2]), "=r"(r[3]) : "r"(addr));
}
// NON-volatile: lets ptxas interleave independent acc chains to hide HMMA latency.
__device__ __forceinline__ void mma_bf16(float* c, const uint32_t* a, uint32_t b0, uint32_t b1) {
    asm("mma.sync.aligned.m16n8k16.row.col.f32.bf16.bf16.f32 "
        "{%0,%1,%2,%3}, {%4,%5,%6,%7}, {%8,%9}, {%0,%1,%2,%3};"
        : "+f"(c[0]), "+f"(c[1]), "+f"(c[2]), "+f"(c[3])
        : "r"(a[0]), "r"(a[1]), "r"(a[2]), "r"(a[3]), "r"(b0), "r"(b1));
}
__device__ __forceinline__ __nv_bfloat162 split_hi2(float a, float b, float* ra, float* rb) {
    __nv_bfloat16 h0 = __float2bfloat16_rn(a), h1 = __float2bfloat16_rn(b);
    *ra = a - __bfloat162float(h0);
    *rb = b - __bfloat162float(h1);
    return __nv_bfloat162(h0, h1);
}
__device__ __forceinline__ uint32_t pack_bf162(__nv_bfloat16 a, __nv_bfloat16 b) {
    __nv_bfloat162 p(a, b);
    return *(uint32_t*)&p;
}

// ---------------- block reduction (256 threads) ----------------
__device__ __forceinline__ float blk_sum(float v) {
    __shared__ float red[8];
    #pragma unroll
    for (int o = 16; o > 0; o >>= 1) v += __shfl_xor_sync(0xffffffffu, v, o);
    int w = threadIdx.x >> 5, l = threadIdx.x & 31;
    if (l == 0) red[w] = v;
    __syncthreads();
    if (w == 0) {
        float r = (l < 8) ? red[l] : 0.0f;
        #pragma unroll
        for (int o = 4; o > 0; o >>= 1) r += __shfl_xor_sync(0xffffffffu, r, o);
        if (l == 0) red[0] = r;
    }
    __syncthreads();
    float out = red[0];
    __syncthreads();
    return out;
}

// ---------------- fp32 -> bf16 hi/lo splits: data + 4 weight matrices, one launch ----------------
__global__ __launch_bounds__(256) void split_all(const float* __restrict__ data,
                                                 const float* __restrict__ Wq, const float* __restrict__ Wk,
                                                 const float* __restrict__ Wv, const float* __restrict__ Wo) {
    int blk = blockIdx.x;
    const float* src;
    __nv_bfloat16 *hi, *lo;
    int i;
    if (blk < 2048) {                       // data: 524288 float4
        src = data; hi = g_dh; lo = g_dl;
        i = blk * 256 + threadIdx.x;
    } else {                                // weights: 4 x 262144 float4
        int m = (blk - 2048) >> 10;
        src = (m == 0) ? Wq : (m == 1) ? Wk : (m == 2) ? Wv : Wo;
        hi = (m < 3) ? g_w3h + (size_t)m * 1048576 : g_woh;
        lo = (m < 3) ? g_w3l + (size_t)m * 1048576 : g_wol;
        i = ((blk - 2048) & 1023) * 256 + threadIdx.x;
    }
    float4 x = ((const float4*)src)[i];
    float r0, r1, r2, r3;
    __nv_bfloat162 h01 = split_hi2(x.x, x.y, &r0, &r1);
    __nv_bfloat162 h23 = split_hi2(x.z, x.w, &r2, &r3);
    ((__nv_bfloat162*)hi)[i * 2 + 0] = h01;
    ((__nv_bfloat162*)hi)[i * 2 + 1] = h23;
    ((__nv_bfloat162*)lo)[i * 2 + 0] = __nv_bfloat162(__float2bfloat16_rn(r0), __float2bfloat16_rn(r1));
    ((__nv_bfloat162*)lo)[i * 2 + 1] = __nv_bfloat162(__float2bfloat16_rn(r2), __float2bfloat16_rn(r3));
}

// ================= HMMA GEMM core: 128x128 tile, K-chunk 32, 2-stage single-sync =================
// 8 warps (4m x 2n), warp tile 32x64. Stage = 4 mats x 128 rows x 80 B (32 bf16 + 16 pad).
// K range [k0, k0 + nchunks*32). mode 0: (acc+bias)*scale -> bf16 hi/lo. mode 2: raw fp32 partials.
#define GSTG       40960
#define GMAT       10240
#define GEMM_SMEM  (2 * GSTG)

__device__ __forceinline__ void hmma_gemm_body(const __nv_bfloat16* __restrict__ Ah,
                                               const __nv_bfloat16* __restrict__ Al,
                                               const __nv_bfloat16* __restrict__ Wh,
                                               const __nv_bfloat16* __restrict__ Wl,
                                               int k0, int nchunks,
                                               const float* __restrict__ bias,
                                               float scale, int mode,
                                               float* __restrict__ Cpart,
                                               __nv_bfloat16* __restrict__ Chi,
                                               __nv_bfloat16* __restrict__ Clo) {
    extern __shared__ __align__(16) char gsm[];
    uint32_t ub = smem_to_u32(gsm);
    int tid = threadIdx.x, lane = tid & 31, wid = tid >> 5;
    int wm = wid & 3, wn = wid >> 2;
    int m0 = blockIdx.y << 7, n0 = blockIdx.x << 7;

    const __nv_bfloat16* srcs[4] = {
        Ah + (size_t)m0 * Dd + k0, Al + (size_t)m0 * Dd + k0,
        Wh + (size_t)n0 * Dd + k0, Wl + (size_t)n0 * Dd + k0 };

    float acc[2][8][4];
    #pragma unroll
    for (int i = 0; i < 2; i++)
        #pragma unroll
        for (int j = 0; j < 8; j++)
            #pragma unroll
            for (int k = 0; k < 4; k++) acc[i][j][k] = 0.0f;

    // per-thread cp slots: 2048 cp16/stage -> 8 per thread
    #pragma unroll
    for (int s = 0; s < 8; s++) {
        int idx = tid + (s << 8);
        int mat = idx >> 9, row = (idx >> 2) & 127, seg = idx & 3;
        cp16(ub + mat * GMAT + row * 80 + seg * 16,
             srcs[mat] + (size_t)row * Dd + seg * 8);
    }
    CP_COMMIT();

    int rsel = lane & 15;
    int cselb = ((lane >> 4) << 4);   // 0 or 16

    for (int c = 0; c < nchunks; c++) {
        int st = c & 1;
        CP_WAIT0();
        __syncthreads();
        if (c + 1 < nchunks) {
            int nst = st ^ 1, kc = (c + 1) << 5;
            #pragma unroll
            for (int s = 0; s < 8; s++) {
                int idx = tid + (s << 8);
                int mat = idx >> 9, row = (idx >> 2) & 127, seg = idx & 3;
                cp16(ub + nst * GSTG + mat * GMAT + row * 80 + seg * 16,
                     srcs[mat] + (size_t)row * Dd + kc + seg * 8);
            }
            CP_COMMIT();
        }

        uint32_t base = ub + st * GSTG;
        #pragma unroll
        for (int kk = 0; kk < 2; kk++) {
            uint32_t ah[2][4], al[2][4];
            #pragma unroll
            for (int mb = 0; mb < 2; mb++) {
                int row = wm * 32 + mb * 16 + rsel;
                ldsm_x4(ah[mb], base + row * 80 + kk * 32 + cselb);
                ldsm_x4(al[mb], base + GMAT + row * 80 + kk * 32 + cselb);
            }
            #pragma unroll
            for (int np = 0; np < 4; np++) {
                uint32_t bh[4], bl[4];
                int row = wn * 64 + np * 16 + rsel;
                ldsm_x4(bh, base + 2 * GMAT + row * 80 + kk * 32 + cselb);
                ldsm_x4(bl, base + 3 * GMAT + row * 80 + kk * 32 + cselb);
                #pragma unroll
                for (int mb = 0; mb < 2; mb++) {
                    mma_bf16(acc[mb][2 * np + 0], ah[mb], bh[0], bh[2]);
                    mma_bf16(acc[mb][2 * np + 1], ah[mb], bh[1], bh[3]);
                    mma_bf16(acc[mb][2 * np + 0], ah[mb], bl[0], bl[2]);
                    mma_bf16(acc[mb][2 * np + 1], ah[mb], bl[1], bl[3]);
                    mma_bf16(acc[mb][2 * np + 0], al[mb], bh[0], bh[2]);
                    mma_bf16(acc[mb][2 * np + 1], al[mb], bh[1], bh[3]);
                }
            }
        }
    }

    #pragma unroll
    for (int mb = 0; mb < 2; mb++) {
        int r0 = m0 + wm * 32 + mb * 16 + (lane >> 2);
        #pragma unroll
        for (int nb = 0; nb < 8; nb++) {
            int col = n0 + wn * 64 + nb * 8 + ((lane & 3) << 1);
            if (mode == 2) {
                *(float2*)(Cpart + (size_t)r0 * Dd + col)       = make_float2(acc[mb][nb][0], acc[mb][nb][1]);
                *(float2*)(Cpart + (size_t)(r0 + 8) * Dd + col) = make_float2(acc[mb][nb][2], acc[mb][nb][3]);
            } else {
                float b0 = bias[col], b1 = bias[col + 1];
                float x0 = (acc[mb][nb][0] + b0) * scale, x1 = (acc[mb][nb][1] + b1) * scale;
                float x2 = (acc[mb][nb][2] + b0) * scale, x3 = (acc[mb][nb][3] + b1) * scale;
                float l0, l1, l2, l3;
                __nv_bfloat162 h01 = split_hi2(x0, x1, &l0, &l1);
                __nv_bfloat162 h23 = split_hi2(x2, x3, &l2, &l3);
                *(__nv_bfloat162*)(Chi + (size_t)r0 * Dd + col)       = h01;
                *(__nv_bfloat162*)(Chi + (size_t)(r0 + 8) * Dd + col) = h23;
                *(__nv_bfloat162*)(Clo + (size_t)r0 * Dd + col) =
                    __nv_bfloat162(__float2bfloat16_rn(l0), __float2bfloat16_rn(l1));
                *(__nv_bfloat162*)(Clo + (size_t)(r0 + 8) * Dd + col) =
                    __nv_bfloat162(__float2bfloat16_rn(l2), __float2bfloat16_rn(l3));
            }
        }
    }
}

// qkv: full-K, bf16 hi/lo epilogue (round-11 proven config)
__global__ __launch_bounds__(256, 2) void qkv_tc(const float* __restrict__ bq,
                                                 const float* __restrict__ bk,
                                                 const float* __restrict__ bv) {
    int z = blockIdx.z;
    const __nv_bfloat16* Wh = g_w3h + (size_t)z * 1048576;
    const __nv_bfloat16* Wl = g_w3l + (size_t)z * 1048576;
    const float* bias = (z == 0) ? bq : (z == 1) ? bk : bv;
    __nv_bfloat16* Chi = (z == 0) ? g_qh : (z == 1) ? g_kh : g_vh;
    __nv_bfloat16* Clo = (z == 0) ? g_ql : (z == 1) ? g_kl : g_vl;
    float scale = (z == 0) ? 0.125f : 1.0f;
    hmma_gemm_body(g_dh, g_dl, Wh, Wl, 0, 32, bias, scale, 0, nullptr, Chi, Clo);
}

// out: split-K=2 (fixes 0.43-wave quantization), raw partials
__global__ __launch_bounds__(256, 2) void out_tc() {
    int kh = blockIdx.z;
    float* Cpart = g_part + (size_t)kh * 2097152;
    hmma_gemm_body(g_aoh, g_aol, g_woh, g_wol, kh * 512, 16, nullptr, 1.0f, 2, Cpart, nullptr, nullptr);
}

__global__ __launch_bounds__(256) void reduce_out(const float* __restrict__ bo,
                                                  float* __restrict__ out) {
    size_t p = (size_t)blockIdx.x * 256 + threadIdx.x;   // 524288 float4 total
    const float4* P = (const float4*)g_part;
    float4 a = P[p];
    float4 b = P[524288 + p];
    float4 bi = *(const float4*)(bo + ((p & 255) << 2));
    ((float4*)out)[p] = make_float4(a.x + b.x + bi.x, a.y + b.y + bi.y,
                                    a.z + b.z + bi.z, a.w + b.w + bi.w);
}

// ================= fused attention: scores+traj -> exp -> PV, flash-style =================
// NOW 3 CTAs/SM (smem 3x56KB=168KB, regs capped 85) to cut the 1.73-wave tail and add warps.
#define AQH 0
#define AQL 9216
#define ASTG(st) (18432 + (st) * 18432)
#define ARS 55296
#define AIV 55808
#define ATTN_SMEM 56064

__global__ __launch_bounds__(256, 3) void attn_fused() {
    extern __shared__ __align__(16) char sm[];
    uint32_t ub = smem_to_u32(sm);
    int tid = threadIdx.x, lane = tid & 31, wid = tid >> 5;
    int wm = wid & 3, wn = wid >> 2;
    int g = lane >> 2, t = lane & 3;
    int rsel = lane & 15, csel = (lane >> 4) << 3;
    int bh = blockIdx.y, b = bh >> 4, h = bh & 15;
    int i0 = blockIdx.x << 6;

    const __nv_bfloat16* kvsrc[4] = { g_kh, g_kl, g_vh, g_vl };
    #pragma unroll
    for (int s = 0; s < 4; s++) {
        int idx = tid + (s << 8);
        int mat = idx >> 9, row = (idx >> 3) & 63, seg = idx & 7;
        const __nv_bfloat16* src = (mat == 0 ? g_qh : g_ql) +
            ((size_t)(b * Nn + i0 + row)) * Dd + h * HDd + seg * 8;
        cp16(ub + (mat ? AQL : AQH) + (row * 72 + seg * 8) * 2, src);
    }
    #pragma unroll
    for (int s = 0; s < 4; s++) {
        int idx = tid + (s << 8);
        int mat = idx >> 8, row = (idx >> 3) & 31, seg = idx & 7;
        const __nv_bfloat16* src = kvsrc[mat] + ((size_t)(b * Nn + row)) * Dd + h * HDd + seg * 8;
        cp16(ub + ASTG(0) + mat * 4608 + (row * 72 + seg * 8) * 2, src);
    }
    CP_COMMIT();

    float pacc[8][4];
    #pragma unroll
    for (int i = 0; i < 8; i++)
        #pragma unroll
        for (int j = 0; j < 4; j++) pacc[i][j] = 0.0f;
    float rs0 = 0.0f, rs1 = 0.0f;

    int i_r0 = i0 + wm * 16 + g;

    for (int c = 0; c < 32; c++) {
        int st = c & 1;
        CP_WAIT0();
        __syncthreads();
        if (c < 31) {
            int jc1 = (c + 1) << 5, nst = st ^ 1;
            #pragma unroll
            for (int s = 0; s < 4; s++) {
                int idx = tid + (s << 8);
                int mat = idx >> 8, row = (idx >> 3) & 31, seg = idx & 7;
                const __nv_bfloat16* src = kvsrc[mat] +
                    ((size_t)(b * Nn + jc1 + row)) * Dd + h * HDd + seg * 8;
                cp16(ub + ASTG(nst) + mat * 4608 + (row * 72 + seg * 8) * 2, src);
            }
            CP_COMMIT();
        }

        uint32_t kbase = ub + ASTG(st);
        int jc = c << 5;

        float sacc0[4] = {0.f, 0.f, 0.f, 0.f};
        float sacc1[4] = {0.f, 0.f, 0.f, 0.f};
        #pragma unroll
        for (int k = 0; k < 4; k++) {
            uint32_t qh[4], ql[4], kh[4], kl[4];
            uint32_t qaddr = (uint32_t)(((wm * 16 + rsel) * 72 + k * 16 + csel) * 2);
            uint32_t kaddr = (uint32_t)(((wn * 16 + rsel) * 72 + k * 16 + csel) * 2);
            ldsm_x4(qh, ub + AQH + qaddr);
            ldsm_x4(ql, ub + AQL + qaddr);
            ldsm_x4(kh, kbase + kaddr);
            ldsm_x4(kl, kbase + 4608 + kaddr);
            mma_bf16(sacc0, qh, kh[0], kh[2]); mma_bf16(sacc1, qh, kh[1], kh[3]);
            mma_bf16(sacc0, qh, kl[0], kl[2]); mma_bf16(sacc1, qh, kl[1], kl[3]);
            mma_bf16(sacc0, ql, kh[0], kh[2]); mma_bf16(sacc1, ql, kh[1], kh[3]);
        }

        uint32_t ah[4], al[4];
        {
            float* sa = sacc0;
            #pragma unroll
            for (int nt = 0; nt < 2; nt++) {
                int jj = jc + wn * 16 + nt * 8 + 2 * t;
                float2 tv0 = *(const float2*)(g_traj + (size_t)i_r0 * Nn + jj);
                float2 tv1 = *(const float2*)(g_traj + (size_t)(i_r0 + 8) * Nn + jj);
                float e0 = __expf(sa[0] + tv0.x), e1 = __expf(sa[1] + tv0.y);
                float e2 = __expf(sa[2] + tv1.x), e3 = __expf(sa[3] + tv1.y);
                rs0 += e0 + e1; rs1 += e2 + e3;
                __nv_bfloat16 h0 = __float2bfloat16_rn(e0), h1 = __float2bfloat16_rn(e1);
                __nv_bfloat16 h2 = __float2bfloat16_rn(e2), h3 = __float2bfloat16_rn(e3);
                float l0 = e0 - __bfloat162float(h0), l1 = e1 - __bfloat162float(h1);
                float l2 = e2 - __bfloat162float(h2), l3 = e3 - __bfloat162float(h3);
                *(__nv_bfloat162*)(g_eh + ((size_t)bh * Nn + i_r0) * Nn + jj)     = __nv_bfloat162(h0, h1);
                *(__nv_bfloat162*)(g_eh + ((size_t)bh * Nn + i_r0 + 8) * Nn + jj) = __nv_bfloat162(h2, h3);
                ah[nt * 2 + 0] = pack_bf162(h0, h1);
                ah[nt * 2 + 1] = pack_bf162(h2, h3);
                al[nt * 2 + 0] = pack_bf162(__float2bfloat16_rn(l0), __float2bfloat16_rn(l1));
                al[nt * 2 + 1] = pack_bf162(__float2bfloat16_rn(l2), __float2bfloat16_rn(l3));
                sa = sacc1;
            }
        }

        #pragma unroll
        for (int db = 0; db < 4; db++) {
            uint32_t vh[4], vl[4];
            uint32_t vaddr = (uint32_t)(((wn * 16 + rsel) * 72 + db * 16 + csel) * 2);
            ldsm_x4_t(vh, kbase + 9216 + vaddr);
            ldsm_x4_t(vl, kbase + 13824 + vaddr);
            mma_bf16(pacc[2 * db + 0], ah, vh[0], vh[1]); mma_bf16(pacc[2 * db + 1], ah, vh[2], vh[3]);
            mma_bf16(pacc[2 * db + 0], al, vh[0], vh[1]); mma_bf16(pacc[2 * db + 1], al, vh[2], vh[3]);
            mma_bf16(pacc[2 * db + 0], ah, vl[0], vl[1]); mma_bf16(pacc[2 * db + 1], ah, vl[2], vl[3]);
        }
    }

    rs0 += __shfl_xor_sync(0xffffffffu, rs0, 1);
    rs0 += __shfl_xor_sync(0xffffffffu, rs0, 2);
    rs1 += __shfl_xor_sync(0xffffffffu, rs1, 1);
    rs1 += __shfl_xor_sync(0xffffffffu, rs1, 2);
    float* s_rs = (float*)(sm + ARS);
    float* s_iv = (float*)(sm + AIV);
    if (t == 0) {
        s_rs[wn * 64 + wm * 16 + g]     = rs0;
        s_rs[wn * 64 + wm * 16 + g + 8] = rs1;
    }
    __syncthreads();
    if (tid < 64) {
        float s = s_rs[tid] + s_rs[64 + tid];
        float inv = 1.0f / s;
        s_iv[tid] = inv;
        g_invs[(size_t)bh * Nn + i0 + tid] = inv;
    }
    __syncthreads();

    float* red = (float*)(sm + ASTG(0)) + wm * 1056;
    if (wn == 0) {
        #pragma unroll
        for (int nt = 0; nt < 8; nt++) {
            int col = nt * 8 + 2 * t;
            red[g * 66 + col]           = pacc[nt][0];
            red[g * 66 + col + 1]       = pacc[nt][1];
            red[(g + 8) * 66 + col]     = pacc[nt][2];
            red[(g + 8) * 66 + col + 1] = pacc[nt][3];
        }
    }
    __syncthreads();
    if (wn == 1) {
        float inv0 = s_iv[wm * 16 + g], inv1 = s_iv[wm * 16 + g + 8];
        #pragma unroll
        for (int nt = 0; nt < 8; nt++) {
            int col = nt * 8 + 2 * t;
            float x0 = (pacc[nt][0] + red[g * 66 + col])           * inv0;
            float x1 = (pacc[nt][1] + red[g * 66 + col + 1])       * inv0;
            float x2 = (pacc[nt][2] + red[(g + 8) * 66 + col])     * inv1;
            float x3 = (pacc[nt][3] + red[(g + 8) * 66 + col + 1]) * inv1;
            float l0, l1, l2, l3;
            __nv_bfloat162 h01 = split_hi2(x0, x1, &l0, &l1);
            __nv_bfloat162 h23 = split_hi2(x2, x3, &l2, &l3);
            size_t o0 = ((size_t)b * Nn + i_r0) * Dd + h * HDd + col;
            size_t o1 = ((size_t)b * Nn + i_r0 + 8) * Dd + h * HDd + col;
            *(__nv_bfloat162*)(g_aoh + o0) = h01;
            *(__nv_bfloat162*)(g_aoh + o1) = h23;
            *(__nv_bfloat162*)(g_aol + o0) = __nv_bfloat162(__float2bfloat16_rn(l0), __float2bfloat16_rn(l1));
            *(__nv_bfloat162*)(g_aol + o1) = __nv_bfloat162(__float2bfloat16_rn(l2), __float2bfloat16_rn(l3));
        }
    }
}

// ---------------- entropy + certainty ----------------
__global__ __launch_bounds__(256) void entropy_kernel(const float* __restrict__ cert,
                                                      float* __restrict__ out_cert) {
    int bi = blockIdx.x;
    int b = bi >> 10, i = bi & 1023;
    int tid = threadIdx.x;

    float a0 = 0.f, a1 = 0.f, a2 = 0.f, a3 = 0.f;
    #pragma unroll
    for (int hh = 0; hh < NHh; hh++) {
        int bh = b * NHh + hh;
        float inv = g_invs[(size_t)bh * Nn + i];
        const __nv_bfloat162* row = (const __nv_bfloat162*)(g_eh + ((size_t)bh * Nn + i) * Nn);
        __nv_bfloat162 v0 = row[tid * 2], v1 = row[tid * 2 + 1];
        a0 += __bfloat162float(v0.x) * inv;
        a1 += __bfloat162float(v0.y) * inv;
        a2 += __bfloat162float(v1.x) * inv;
        a3 += __bfloat162float(v1.y) * inv;
    }
    a0 *= (1.0f / NHh); a1 *= (1.0f / NHh); a2 *= (1.0f / NHh); a3 *= (1.0f / NHh);
    float hl = 0.0f;
    a0 = fmaxf(a0, 1e-10f); hl -= a0 * __logf(a0);
    a1 = fmaxf(a1, 1e-10f); hl -= a1 * __logf(a1);
    a2 = fmaxf(a2, 1e-10f); hl -= a2 * __logf(a2);
    a3 = fmaxf(a3, 1e-10f); hl -= a3 * __logf(a3);
    float H = blk_sum(hl);
    if (tid == 0) {
        float sig = 1.0f / (1.0f + __expf(H - 6.9314718055994531f));
        out_cert[bi] = fmaxf(cert[bi], sig);
    }
}

// ---------------- trajectory pairwise similarity ----------------
__device__ __forceinline__ float fast_sqrt(float x) {
    return x * rsqrtf(x + 1e-30f);
}

__global__ __launch_bounds__(1024) void traj_kernel(const float* __restrict__ pos,
                                                    const float* __restrict__ quat) {
    __shared__ float Pi[3][BT][32], Pj[3][BT][32];
    __shared__ float Qi[4][BT][32], Qj[4][BT][32];
    int i0 = blockIdx.y * 32, j0 = blockIdx.x * 32;
    int tid = threadIdx.y * 32 + threadIdx.x;

    for (int idx = tid; idx < BT * 32; idx += 1024) {
        int bt = idx >> 5, r = idx & 31;
        size_t pi = ((size_t)bt * Nn + i0 + r) * 3;
        size_t pj = ((size_t)bt * Nn + j0 + r) * 3;
        Pi[0][bt][r] = pos[pi + 0]; Pi[1][bt][r] = pos[pi + 1]; Pi[2][bt][r] = pos[pi + 2];
        Pj[0][bt][r] = pos[pj + 0]; Pj[1][bt][r] = pos[pj + 1]; Pj[2][bt][r] = pos[pj + 2];
        size_t qi = ((size_t)bt * Nn + i0 + r) * 4;
        size_t qj = ((size_t)bt * Nn + j0 + r) * 4;
        Qi[0][bt][r] = quat[qi + 0]; Qi[1][bt][r] = quat[qi + 1];
        Qi[2][bt][r] = quat[qi + 2]; Qi[3][bt][r] = quat[qi + 3];
        Qj[0][bt][r] = quat[qj + 0]; Qj[1][bt][r] = quat[qj + 1];
        Qj[2][bt][r] = quat[qj + 2]; Qj[3][bt][r] = quat[qj + 3];
    }
    __syncthreads();

    int ti = threadIdx.y, tj = threadIdx.x;
    float spd = 0.0f, sqm = 0.0f, sqp = 0.0f;
    #pragma unroll
    for (int bt = 0; bt < BT; bt++) {
        float dx = Pi[0][bt][ti] - Pj[0][bt][tj];
        float dy = Pi[1][bt][ti] - Pj[1][bt][tj];
        float dz = Pi[2][bt][ti] - Pj[2][bt][tj];
        spd += fast_sqrt(dx * dx + dy * dy + dz * dz);
        float a0 = Qi[0][bt][ti], a1 = Qi[1][bt][ti], a2 = Qi[2][bt][ti], a3 = Qi[3][bt][ti];
        float b0 = Qj[0][bt][tj], b1 = Qj[1][bt][tj], b2 = Qj[2][bt][tj], b3 = Qj[3][bt][tj];
        float m0 = a0 - b0, m1 = a1 - b1, m2 = a2 - b2, m3 = a3 - b3;
        float p0 = a0 + b0, p1 = a1 + b1, p2 = a2 + b2, p3 = a3 + b3;
        sqm += fast_sqrt(m0 * m0 + m1 * m1 + m2 * m2 + m3 * m3);
        sqp += fast_sqrt(p0 * p0 + p1 * p1 + p2 * p2 + p3 * p3);
    }
    float pd = spd * (1.0f / BT);
    float qd = fminf(sqm, sqp) * (1.0f / BT);
    g_traj[(size_t)(i0 + ti) * Nn + (j0 + tj)] = __expf(-(pd + qd));
}

// ---------------- row-normalize traj (folds in 0.5 bias scale) ----------------
__global__ __launch_bounds__(256) void traj_norm_kernel() {
    float* row = g_traj + (size_t)blockIdx.x * Nn;
    float4 v = ((const float4*)row)[threadIdx.x];
    float s = blk_sum(v.x + v.y + v.z + v.w);
    float sc = 0.5f / s;
    v.x *= sc; v.y *= sc; v.z *= sc; v.w *= sc;
    ((float4*)row)[threadIdx.x] = v;
}

// ---------------- launch ----------------
extern "C" void kernel_launch(void* const* d_in, const int* in_sizes, int n_in,
                              void* d_out, int out_size) {
    const float* data  = (const float*)d_in[0];
    const float* tpos  = (const float*)d_in[1];
    const float* tquat = (const float*)d_in[2];
    const float* cert  = (const float*)d_in[3];
    const float* Wq = (const float*)d_in[4];  const float* bq = (const float*)d_in[5];
    const float* Wk = (const float*)d_in[6];  const float* bk = (const float*)d_in[7];
    const float* Wv = (const float*)d_in[8];  const float* bv = (const float*)d_in[9];
    const float* Wo = (const float*)d_in[10]; const float* bo = (const float*)d_in[11];
    float* out = (float*)d_out;

    // idempotent, host-side, capture-safe (no enqueue, no allocation)
    cudaFuncSetAttribute(attn_fused, cudaFuncAttributeMaxDynamicSharedMemorySize, ATTN_SMEM);
    cudaFuncSetAttribute(qkv_tc, cudaFuncAttributeMaxDynamicSharedMemorySize, GEMM_SMEM);
    cudaFuncSetAttribute(out_tc, cudaFuncAttributeMaxDynamicSharedMemorySize, GEMM_SMEM);

    split_all<<<6144, 256>>>(data, Wq, Wk, Wv, Wo);
    traj_kernel<<<dim3(32, 32), dim3(32, 32)>>>(tpos, tquat);
    traj_norm_kernel<<<Nn, 256>>>();
    qkv_tc<<<dim3(8, 16, 3), 256, GEMM_SMEM>>>(bq, bk, bv);   // slot 4: ncu captures this
    attn_fused<<<dim3(16, 32), 256, ATTN_SMEM>>>();
    entropy_kernel<<<Bb * Nn, 256>>>(cert, out + (size_t)Bb * Nn * Dd);
    out_tc<<<dim3(8, 16, 2), 256, GEMM_SMEM>>>();
    reduce_out<<<2048, 256>>>(bo, out);
}

// round 14
// speedup vs baseline: 1.0070x; 1.0042x over previous
#include <cuda_runtime.h>
#include <cuda_bf16.h>
#include <math.h>
#include <stdint.h>

#define Bb  2
#define Tt  10
#define Nn  1024
#define Dd  1024
#define NHh 16
#define HDd 64
#define BT  (Bb*Tt)

// ---------------- scratch (static device globals; no allocation) ----------------
__device__ float g_traj[(size_t)Nn * Nn];

// bf16 hi/lo operand pairs
__device__ __nv_bfloat16 g_dh[(size_t)Bb * Nn * Dd],  g_dl[(size_t)Bb * Nn * Dd];
__device__ __nv_bfloat16 g_w3h[(size_t)3 * Dd * Dd],  g_w3l[(size_t)3 * Dd * Dd];
__device__ __nv_bfloat16 g_woh[(size_t)Dd * Dd],      g_wol[(size_t)Dd * Dd];
__device__ __nv_bfloat16 g_qh[(size_t)Bb * Nn * Dd],  g_ql[(size_t)Bb * Nn * Dd];   // Q/8
__device__ __nv_bfloat16 g_kh[(size_t)Bb * Nn * Dd],  g_kl[(size_t)Bb * Nn * Dd];
__device__ __nv_bfloat16 g_vh[(size_t)Bb * Nn * Dd],  g_vl[(size_t)Bb * Nn * Dd];
__device__ __nv_bfloat16 g_aoh[(size_t)Bb * Nn * Dd], g_aol[(size_t)Bb * Nn * Dd];
// unnormalized exp(scores) hi part (for entropy) + per-row 1/rowsum
__device__ __nv_bfloat16 g_eh[(size_t)Bb * NHh * Nn * Nn];
__device__ float g_invs[(size_t)Bb * NHh * Nn];
// split-K fp32 partials (out projection only)
__device__ float g_part[(size_t)2 * Bb * Nn * Dd];

// ================= HMMA helpers =================
__device__ __forceinline__ uint32_t smem_to_u32(const void* p) {
    uint32_t a;
    asm("{ .reg .u64 t; cvta.to.shared.u64 t, %1; cvt.u32.u64 %0, t; }" : "=r"(a) : "l"(p));
    return a;
}
__device__ __forceinline__ void cp16(uint32_t dst, const void* src) {
    asm volatile("cp.async.cg.shared.global [%0], [%1], 16;" :: "r"(dst), "l"(src));
}
#define CP_COMMIT() asm volatile("cp.async.commit_group;" ::: "memory")
#define CP_WAIT0()  asm volatile("cp.async.wait_group 0;" ::: "memory")

__device__ __forceinline__ void ldsm_x4(uint32_t* r, uint32_t addr) {
    asm volatile("ldmatrix.sync.aligned.m8n8.x4.shared.b16 {%0,%1,%2,%3}, [%4];"
                 : "=r"(r[0]), "=r"(r[1]), "=r"(r[2]), "=r"(r[3]) : "r"(addr));
}
__device__ __forceinline__ void ldsm_x4_t(uint32_t* r, uint32_t addr) {
    asm volatile("ldmatrix.sync.aligned.m8n8.x4.trans.shared.b16 {%0,%1,%2,%3}, [%4];"
                 : "=r"(r[0]), "=r"(r[1]), "=r"(r[2]), "=r"(r[3]) : "r"(addr));
}
// NON-volatile: lets ptxas interleave independent acc chains to hide HMMA latency.
__device__ __forceinline__ void mma_bf16(float* c, const uint32_t* a, uint32_t b0, uint32_t b1) {
    asm("mma.sync.aligned.m16n8k16.row.col.f32.bf16.bf16.f32 "
        "{%0,%1,%2,%3}, {%4,%5,%6,%7}, {%8,%9}, {%0,%1,%2,%3};"
        : "+f"(c[0]), "+f"(c[1]), "+f"(c[2]), "+f"(c[3])
        : "r"(a[0]), "r"(a[1]), "r"(a[2]), "r"(a[3]), "r"(b0), "r"(b1));
}
__device__ __forceinline__ __nv_bfloat162 split_hi2(float a, float b, float* ra, float* rb) {
    __nv_bfloat16 h0 = __float2bfloat16_rn(a), h1 = __float2bfloat16_rn(b);
    *ra = a - __bfloat162float(h0);
    *rb = b - __bfloat162float(h1);
    return __nv_bfloat162(h0, h1);
}
__device__ __forceinline__ uint32_t pack_bf162(__nv_bfloat16 a, __nv_bfloat16 b) {
    __nv_bfloat162 p(a, b);
    return *(uint32_t*)&p;
}

// ---------------- block reduction (256 threads) ----------------
__device__ __forceinline__ float blk_sum(float v) {
    __shared__ float red[8];
    #pragma unroll
    for (int o = 16; o > 0; o >>= 1) v += __shfl_xor_sync(0xffffffffu, v, o);
    int w = threadIdx.x >> 5, l = threadIdx.x & 31;
    if (l == 0) red[w] = v;
    __syncthreads();
    if (w == 0) {
        float r = (l < 8) ? red[l] : 0.0f;
        #pragma unroll
        for (int o = 4; o > 0; o >>= 1) r += __shfl_xor_sync(0xffffffffu, r, o);
        if (l == 0) red[0] = r;
    }
    __syncthreads();
    float out = red[0];
    __syncthreads();
    return out;
}

__device__ __forceinline__ float fast_sqrt(float x) {
    return x * rsqrtf(x + 1e-30f);
}

// ================= merged prep: bf16 splits (blocks 0..1535) + traj tiles (1536..2559) =================
__global__ __launch_bounds__(1024) void prep_kernel(const float* __restrict__ data,
                                                    const float* __restrict__ Wq, const float* __restrict__ Wk,
                                                    const float* __restrict__ Wv, const float* __restrict__ Wo,
                                                    const float* __restrict__ pos,
                                                    const float* __restrict__ quat) {
    __shared__ float Pi[3][BT][32], Pj[3][BT][32];
    __shared__ float Qi[4][BT][32], Qj[4][BT][32];
    int tid = threadIdx.x;

    if (blockIdx.x < 1536) {
        // ---- split role (identical math to split_all; 1024 threads = 4 old 256-thread blocks)
        int oblk = (blockIdx.x << 2) | (tid >> 8);
        int ot = tid & 255;
        const float* src;
        __nv_bfloat16 *hi, *lo;
        int i;
        if (oblk < 2048) {
            src = data; hi = g_dh; lo = g_dl;
            i = oblk * 256 + ot;
        } else {
            int m = (oblk - 2048) >> 10;
            src = (m == 0) ? Wq : (m == 1) ? Wk : (m == 2) ? Wv : Wo;
            hi = (m < 3) ? g_w3h + (size_t)m * 1048576 : g_woh;
            lo = (m < 3) ? g_w3l + (size_t)m * 1048576 : g_wol;
            i = ((oblk - 2048) & 1023) * 256 + ot;
        }
        float4 x = ((const float4*)src)[i];
        float r0, r1, r2, r3;
        __nv_bfloat162 h01 = split_hi2(x.x, x.y, &r0, &r1);
        __nv_bfloat162 h23 = split_hi2(x.z, x.w, &r2, &r3);
        ((__nv_bfloat162*)hi)[i * 2 + 0] = h01;
        ((__nv_bfloat162*)hi)[i * 2 + 1] = h23;
        ((__nv_bfloat162*)lo)[i * 2 + 0] = __nv_bfloat162(__float2bfloat16_rn(r0), __float2bfloat16_rn(r1));
        ((__nv_bfloat162*)lo)[i * 2 + 1] = __nv_bfloat162(__float2bfloat16_rn(r2), __float2bfloat16_rn(r3));
        return;
    }

    // ---- traj role (identical math to traj_kernel)
    int bIdx = blockIdx.x - 1536;
    int i0 = (bIdx >> 5) * 32, j0 = (bIdx & 31) * 32;

    for (int idx = tid; idx < BT * 32; idx += 1024) {
        int bt = idx >> 5, r = idx & 31;
        size_t pi = ((size_t)bt * Nn + i0 + r) * 3;
        size_t pj = ((size_t)bt * Nn + j0 + r) * 3;
        Pi[0][bt][r] = pos[pi + 0]; Pi[1][bt][r] = pos[pi + 1]; Pi[2][bt][r] = pos[pi + 2];
        Pj[0][bt][r] = pos[pj + 0]; Pj[1][bt][r] = pos[pj + 1]; Pj[2][bt][r] = pos[pj + 2];
        size_t qi = ((size_t)bt * Nn + i0 + r) * 4;
        size_t qj = ((size_t)bt * Nn + j0 + r) * 4;
        Qi[0][bt][r] = quat[qi + 0]; Qi[1][bt][r] = quat[qi + 1];
        Qi[2][bt][r] = quat[qi + 2]; Qi[3][bt][r] = quat[qi + 3];
        Qj[0][bt][r] = quat[qj + 0]; Qj[1][bt][r] = quat[qj + 1];
        Qj[2][bt][r] = quat[qj + 2]; Qj[3][bt][r] = quat[qj + 3];
    }
    __syncthreads();

    int ti = tid >> 5, tj = tid & 31;
    float spd = 0.0f, sqm = 0.0f, sqp = 0.0f;
    #pragma unroll
    for (int bt = 0; bt < BT; bt++) {
        float dx = Pi[0][bt][ti] - Pj[0][bt][tj];
        float dy = Pi[1][bt][ti] - Pj[1][bt][tj];
        float dz = Pi[2][bt][ti] - Pj[2][bt][tj];
        spd += fast_sqrt(dx * dx + dy * dy + dz * dz);
        float a0 = Qi[0][bt][ti], a1 = Qi[1][bt][ti], a2 = Qi[2][bt][ti], a3 = Qi[3][bt][ti];
        float b0 = Qj[0][bt][tj], b1 = Qj[1][bt][tj], b2 = Qj[2][bt][tj], b3 = Qj[3][bt][tj];
        float m0 = a0 - b0, m1 = a1 - b1, m2 = a2 - b2, m3 = a3 - b3;
        float p0 = a0 + b0, p1 = a1 + b1, p2 = a2 + b2, p3 = a3 + b3;
        sqm += fast_sqrt(m0 * m0 + m1 * m1 + m2 * m2 + m3 * m3);
        sqp += fast_sqrt(p0 * p0 + p1 * p1 + p2 * p2 + p3 * p3);
    }
    float pd = spd * (1.0f / BT);
    float qd = fminf(sqm, sqp) * (1.0f / BT);
    g_traj[(size_t)(i0 + ti) * Nn + (j0 + tj)] = __expf(-(pd + qd));
}

// ---------------- row-normalize traj (folds in 0.5 bias scale) ----------------
__global__ __launch_bounds__(256) void traj_norm_kernel() {
    float* row = g_traj + (size_t)blockIdx.x * Nn;
    float4 v = ((const float4*)row)[threadIdx.x];
    float s = blk_sum(v.x + v.y + v.z + v.w);
    float sc = 0.5f / s;
    v.x *= sc; v.y *= sc; v.z *= sc; v.w *= sc;
    ((float4*)row)[threadIdx.x] = v;
}

// ================= HMMA GEMM core: 128x128 tile, K-chunk 32, 2-stage single-sync =================
#define GSTG       40960
#define GMAT       10240
#define GEMM_SMEM  (2 * GSTG)

__device__ __forceinline__ void hmma_gemm_body(const __nv_bfloat16* __restrict__ Ah,
                                               const __nv_bfloat16* __restrict__ Al,
                                               const __nv_bfloat16* __restrict__ Wh,
                                               const __nv_bfloat16* __restrict__ Wl,
                                               int k0, int nchunks,
                                               const float* __restrict__ bias,
                                               float scale, int mode,
                                               float* __restrict__ Cpart,
                                               __nv_bfloat16* __restrict__ Chi,
                                               __nv_bfloat16* __restrict__ Clo) {
    extern __shared__ __align__(16) char gsm[];
    uint32_t ub = smem_to_u32(gsm);
    int tid = threadIdx.x, lane = tid & 31, wid = tid >> 5;
    int wm = wid & 3, wn = wid >> 2;
    int m0 = blockIdx.y << 7, n0 = blockIdx.x << 7;

    const __nv_bfloat16* srcs[4] = {
        Ah + (size_t)m0 * Dd + k0, Al + (size_t)m0 * Dd + k0,
        Wh + (size_t)n0 * Dd + k0, Wl + (size_t)n0 * Dd + k0 };

    float acc[2][8][4];
    #pragma unroll
    for (int i = 0; i < 2; i++)
        #pragma unroll
        for (int j = 0; j < 8; j++)
            #pragma unroll
            for (int k = 0; k < 4; k++) acc[i][j][k] = 0.0f;

    #pragma unroll
    for (int s = 0; s < 8; s++) {
        int idx = tid + (s << 8);
        int mat = idx >> 9, row = (idx >> 2) & 127, seg = idx & 3;
        cp16(ub + mat * GMAT + row * 80 + seg * 16,
             srcs[mat] + (size_t)row * Dd + seg * 8);
    }
    CP_COMMIT();

    int rsel = lane & 15;
    int cselb = ((lane >> 4) << 4);

    for (int c = 0; c < nchunks; c++) {
        int st = c & 1;
        CP_WAIT0();
        __syncthreads();
        if (c + 1 < nchunks) {
            int nst = st ^ 1, kc = (c + 1) << 5;
            #pragma unroll
            for (int s = 0; s < 8; s++) {
                int idx = tid + (s << 8);
                int mat = idx >> 9, row = (idx >> 2) & 127, seg = idx & 3;
                cp16(ub + nst * GSTG + mat * GMAT + row * 80 + seg * 16,
                     srcs[mat] + (size_t)row * Dd + kc + seg * 8);
            }
            CP_COMMIT();
        }

        uint32_t base = ub + st * GSTG;
        #pragma unroll
        for (int kk = 0; kk < 2; kk++) {
            uint32_t ah[2][4], al[2][4];
            #pragma unroll
            for (int mb = 0; mb < 2; mb++) {
                int row = wm * 32 + mb * 16 + rsel;
                ldsm_x4(ah[mb], base + row * 80 + kk * 32 + cselb);
                ldsm_x4(al[mb], base + GMAT + row * 80 + kk * 32 + cselb);
            }
            #pragma unroll
            for (int np = 0; np < 4; np++) {
                uint32_t bh[4], bl[4];
                int row = wn * 64 + np * 16 + rsel;
                ldsm_x4(bh, base + 2 * GMAT + row * 80 + kk * 32 + cselb);
                ldsm_x4(bl, base + 3 * GMAT + row * 80 + kk * 32 + cselb);
                #pragma unroll
                for (int mb = 0; mb < 2; mb++) {
                    mma_bf16(acc[mb][2 * np + 0], ah[mb], bh[0], bh[2]);
                    mma_bf16(acc[mb][2 * np + 1], ah[mb], bh[1], bh[3]);
                    mma_bf16(acc[mb][2 * np + 0], ah[mb], bl[0], bl[2]);
                    mma_bf16(acc[mb][2 * np + 1], ah[mb], bl[1], bl[3]);
                    mma_bf16(acc[mb][2 * np + 0], al[mb], bh[0], bh[2]);
                    mma_bf16(acc[mb][2 * np + 1], al[mb], bh[1], bh[3]);
                }
            }
        }
    }

    #pragma unroll
    for (int mb = 0; mb < 2; mb++) {
        int r0 = m0 + wm * 32 + mb * 16 + (lane >> 2);
        #pragma unroll
        for (int nb = 0; nb < 8; nb++) {
            int col = n0 + wn * 64 + nb * 8 + ((lane & 3) << 1);
            if (mode == 2) {
                *(float2*)(Cpart + (size_t)r0 * Dd + col)       = make_float2(acc[mb][nb][0], acc[mb][nb][1]);
                *(float2*)(Cpart + (size_t)(r0 + 8) * Dd + col) = make_float2(acc[mb][nb][2], acc[mb][nb][3]);
            } else {
                float b0 = bias[col], b1 = bias[col + 1];
                float x0 = (acc[mb][nb][0] + b0) * scale, x1 = (acc[mb][nb][1] + b1) * scale;
                float x2 = (acc[mb][nb][2] + b0) * scale, x3 = (acc[mb][nb][3] + b1) * scale;
                float l0, l1, l2, l3;
                __nv_bfloat162 h01 = split_hi2(x0, x1, &l0, &l1);
                __nv_bfloat162 h23 = split_hi2(x2, x3, &l2, &l3);
                *(__nv_bfloat162*)(Chi + (size_t)r0 * Dd + col)       = h01;
                *(__nv_bfloat162*)(Chi + (size_t)(r0 + 8) * Dd + col) = h23;
                *(__nv_bfloat162*)(Clo + (size_t)r0 * Dd + col) =
                    __nv_bfloat162(__float2bfloat16_rn(l0), __float2bfloat16_rn(l1));
                *(__nv_bfloat162*)(Clo + (size_t)(r0 + 8) * Dd + col) =
                    __nv_bfloat162(__float2bfloat16_rn(l2), __float2bfloat16_rn(l3));
            }
        }
    }
}

// qkv: full-K, bf16 hi/lo epilogue (round-11 proven config)
__global__ __launch_bounds__(256, 2) void qkv_tc(const float* __restrict__ bq,
                                                 const float* __restrict__ bk,
                                                 const float* __restrict__ bv) {
    int z = blockIdx.z;
    const __nv_bfloat16* Wh = g_w3h + (size_t)z * 1048576;
    const __nv_bfloat16* Wl = g_w3l + (size_t)z * 1048576;
    const float* bias = (z == 0) ? bq : (z == 1) ? bk : bv;
    __nv_bfloat16* Chi = (z == 0) ? g_qh : (z == 1) ? g_kh : g_vh;
    __nv_bfloat16* Clo = (z == 0) ? g_ql : (z == 1) ? g_kl : g_vl;
    float scale = (z == 0) ? 0.125f : 1.0f;
    hmma_gemm_body(g_dh, g_dl, Wh, Wl, 0, 32, bias, scale, 0, nullptr, Chi, Clo);
}

// out: split-K=2 (fixes 0.43-wave quantization), raw partials
__global__ __launch_bounds__(256, 2) void out_tc() {
    int kh = blockIdx.z;
    float* Cpart = g_part + (size_t)kh * 2097152;
    hmma_gemm_body(g_aoh, g_aol, g_woh, g_wol, kh * 512, 16, nullptr, 1.0f, 2, Cpart, nullptr, nullptr);
}

__global__ __launch_bounds__(256) void reduce_out(const float* __restrict__ bo,
                                                  float* __restrict__ out) {
    size_t p = (size_t)blockIdx.x * 256 + threadIdx.x;
    const float4* P = (const float4*)g_part;
    float4 a = P[p];
    float4 b = P[524288 + p];
    float4 bi = *(const float4*)(bo + ((p & 255) << 2));
    ((float4*)out)[p] = make_float4(a.x + b.x + bi.x, a.y + b.y + bi.y,
                                    a.z + b.z + bi.z, a.w + b.w + bi.w);
}

// ================= fused attention: scores+traj -> exp -> PV, flash-style =================
// 2 CTAs/SM (round-11 proven; 3 CTAs spilled regs and regressed in round 13).
#define AQH 0
#define AQL 9216
#define ASTG(st) (18432 + (st) * 18432)
#define ARS 55296
#define AIV 55808
#define ATTN_SMEM 56064

__global__ __launch_bounds__(256, 2) void attn_fused() {
    extern __shared__ __align__(16) char sm[];
    uint32_t ub = smem_to_u32(sm);
    int tid = threadIdx.x, lane = tid & 31, wid = tid >> 5;
    int wm = wid & 3, wn = wid >> 2;
    int g = lane >> 2, t = lane & 3;
    int rsel = lane & 15, csel = (lane >> 4) << 3;
    int bh = blockIdx.y, b = bh >> 4, h = bh & 15;
    int i0 = blockIdx.x << 6;

    const __nv_bfloat16* kvsrc[4] = { g_kh, g_kl, g_vh, g_vl };
    #pragma unroll
    for (int s = 0; s < 4; s++) {
        int idx = tid + (s << 8);
        int mat = idx >> 9, row = (idx >> 3) & 63, seg = idx & 7;
        const __nv_bfloat16* src = (mat == 0 ? g_qh : g_ql) +
            ((size_t)(b * Nn + i0 + row)) * Dd + h * HDd + seg * 8;
        cp16(ub + (mat ? AQL : AQH) + (row * 72 + seg * 8) * 2, src);
    }
    #pragma unroll
    for (int s = 0; s < 4; s++) {
        int idx = tid + (s << 8);
        int mat = idx >> 8, row = (idx >> 3) & 31, seg = idx & 7;
        const __nv_bfloat16* src = kvsrc[mat] + ((size_t)(b * Nn + row)) * Dd + h * HDd + seg * 8;
        cp16(ub + ASTG(0) + mat * 4608 + (row * 72 + seg * 8) * 2, src);
    }
    CP_COMMIT();

    float pacc[8][4];
    #pragma unroll
    for (int i = 0; i < 8; i++)
        #pragma unroll
        for (int j = 0; j < 4; j++) pacc[i][j] = 0.0f;
    float rs0 = 0.0f, rs1 = 0.0f;

    int i_r0 = i0 + wm * 16 + g;

    for (int c = 0; c < 32; c++) {
        int st = c & 1;
        CP_WAIT0();
        __syncthreads();
        if (c < 31) {
            int jc1 = (c + 1) << 5, nst = st ^ 1;
            #pragma unroll
            for (int s = 0; s < 4; s++) {
                int idx = tid + (s << 8);
                int mat = idx >> 8, row = (idx >> 3) & 31, seg = idx & 7;
                const __nv_bfloat16* src = kvsrc[mat] +
                    ((size_t)(b * Nn + jc1 + row)) * Dd + h * HDd + seg * 8;
                cp16(ub + ASTG(nst) + mat * 4608 + (row * 72 + seg * 8) * 2, src);
            }
            CP_COMMIT();
        }

        uint32_t kbase = ub + ASTG(st);
        int jc = c << 5;

        float sacc0[4] = {0.f, 0.f, 0.f, 0.f};
        float sacc1[4] = {0.f, 0.f, 0.f, 0.f};
        #pragma unroll
        for (int k = 0; k < 4; k++) {
            uint32_t qh[4], ql[4], kh[4], kl[4];
            uint32_t qaddr = (uint32_t)(((wm * 16 + rsel) * 72 + k * 16 + csel) * 2);
            uint32_t kaddr = (uint32_t)(((wn * 16 + rsel) * 72 + k * 16 + csel) * 2);
            ldsm_x4(qh, ub + AQH + qaddr);
            ldsm_x4(ql, ub + AQL + qaddr);
            ldsm_x4(kh, kbase + kaddr);
            ldsm_x4(kl, kbase + 4608 + kaddr);
            mma_bf16(sacc0, qh, kh[0], kh[2]); mma_bf16(sacc1, qh, kh[1], kh[3]);
            mma_bf16(sacc0, qh, kl[0], kl[2]); mma_bf16(sacc1, qh, kl[1], kl[3]);
            mma_bf16(sacc0, ql, kh[0], kh[2]); mma_bf16(sacc1, ql, kh[1], kh[3]);
        }

        uint32_t ah[4], al[4];
        {
            float* sa = sacc0;
            #pragma unroll
            for (int nt = 0; nt < 2; nt++) {
                int jj = jc + wn * 16 + nt * 8 + 2 * t;
                float2 tv0 = *(const float2*)(g_traj + (size_t)i_r0 * Nn + jj);
                float2 tv1 = *(const float2*)(g_traj + (size_t)(i_r0 + 8) * Nn + jj);
                float e0 = __expf(sa[0] + tv0.x), e1 = __expf(sa[1] + tv0.y);
                float e2 = __expf(sa[2] + tv1.x), e3 = __expf(sa[3] + tv1.y);
                rs0 += e0 + e1; rs1 += e2 + e3;
                __nv_bfloat16 h0 = __float2bfloat16_rn(e0), h1 = __float2bfloat16_rn(e1);
                __nv_bfloat16 h2 = __float2bfloat16_rn(e2), h3 = __float2bfloat16_rn(e3);
                float l0 = e0 - __bfloat162float(h0), l1 = e1 - __bfloat162float(h1);
                float l2 = e2 - __bfloat162float(h2), l3 = e3 - __bfloat162float(h3);
                *(__nv_bfloat162*)(g_eh + ((size_t)bh * Nn + i_r0) * Nn + jj)     = __nv_bfloat162(h0, h1);
                *(__nv_bfloat162*)(g_eh + ((size_t)bh * Nn + i_r0 + 8) * Nn + jj) = __nv_bfloat162(h2, h3);
                ah[nt * 2 + 0] = pack_bf162(h0, h1);
                ah[nt * 2 + 1] = pack_bf162(h2, h3);
                al[nt * 2 + 0] = pack_bf162(__float2bfloat16_rn(l0), __float2bfloat16_rn(l1));
                al[nt * 2 + 1] = pack_bf162(__float2bfloat16_rn(l2), __float2bfloat16_rn(l3));
                sa = sacc1;
            }
        }

        #pragma unroll
        for (int db = 0; db < 4; db++) {
            uint32_t vh[4], vl[4];
            uint32_t vaddr = (uint32_t)(((wn * 16 + rsel) * 72 + db * 16 + csel) * 2);
            ldsm_x4_t(vh, kbase + 9216 + vaddr);
            ldsm_x4_t(vl, kbase + 13824 + vaddr);
            mma_bf16(pacc[2 * db + 0], ah, vh[0], vh[1]); mma_bf16(pacc[2 * db + 1], ah, vh[2], vh[3]);
            mma_bf16(pacc[2 * db + 0], al, vh[0], vh[1]); mma_bf16(pacc[2 * db + 1], al, vh[2], vh[3]);
            mma_bf16(pacc[2 * db + 0], ah, vl[0], vl[1]); mma_bf16(pacc[2 * db + 1], ah, vl[2], vl[3]);
        }
    }

    rs0 += __shfl_xor_sync(0xffffffffu, rs0, 1);
    rs0 += __shfl_xor_sync(0xffffffffu, rs0, 2);
    rs1 += __shfl_xor_sync(0xffffffffu, rs1, 1);
    rs1 += __shfl_xor_sync(0xffffffffu, rs1, 2);
    float* s_rs = (float*)(sm + ARS);
    float* s_iv = (float*)(sm + AIV);
    if (t == 0) {
        s_rs[wn * 64 + wm * 16 + g]     = rs0;
        s_rs[wn * 64 + wm * 16 + g + 8] = rs1;
    }
    __syncthreads();
    if (tid < 64) {
        float s = s_rs[tid] + s_rs[64 + tid];
        float inv = 1.0f / s;
        s_iv[tid] = inv;
        g_invs[(size_t)bh * Nn + i0 + tid] = inv;
    }
    __syncthreads();

    float* red = (float*)(sm + ASTG(0)) + wm * 1056;
    if (wn == 0) {
        #pragma unroll
        for (int nt = 0; nt < 8; nt++) {
            int col = nt * 8 + 2 * t;
            red[g * 66 + col]           = pacc[nt][0];
            red[g * 66 + col + 1]       = pacc[nt][1];
            red[(g + 8) * 66 + col]     = pacc[nt][2];
            red[(g + 8) * 66 + col + 1] = pacc[nt][3];
        }
    }
    __syncthreads();
    if (wn == 1) {
        float inv0 = s_iv[wm * 16 + g], inv1 = s_iv[wm * 16 + g + 8];
        #pragma unroll
        for (int nt = 0; nt < 8; nt++) {
            int col = nt * 8 + 2 * t;
            float x0 = (pacc[nt][0] + red[g * 66 + col])           * inv0;
            float x1 = (pacc[nt][1] + red[g * 66 + col + 1])       * inv0;
            float x2 = (pacc[nt][2] + red[(g + 8) * 66 + col])     * inv1;
            float x3 = (pacc[nt][3] + red[(g + 8) * 66 + col + 1]) * inv1;
            float l0, l1, l2, l3;
            __nv_bfloat162 h01 = split_hi2(x0, x1, &l0, &l1);
            __nv_bfloat162 h23 = split_hi2(x2, x3, &l2, &l3);
            size_t o0 = ((size_t)b * Nn + i_r0) * Dd + h * HDd + col;
            size_t o1 = ((size_t)b * Nn + i_r0 + 8) * Dd + h * HDd + col;
            *(__nv_bfloat162*)(g_aoh + o0) = h01;
            *(__nv_bfloat162*)(g_aoh + o1) = h23;
            *(__nv_bfloat162*)(g_aol + o0) = __nv_bfloat162(__float2bfloat16_rn(l0), __float2bfloat16_rn(l1));
            *(__nv_bfloat162*)(g_aol + o1) = __nv_bfloat162(__float2bfloat16_rn(l2), __float2bfloat16_rn(l3));
        }
    }
}

// ---------------- entropy + certainty ----------------
__global__ __launch_bounds__(256) void entropy_kernel(const float* __restrict__ cert,
                                                      float* __restrict__ out_cert) {
    int bi = blockIdx.x;
    int b = bi >> 10, i = bi & 1023;
    int tid = threadIdx.x;

    float a0 = 0.f, a1 = 0.f, a2 = 0.f, a3 = 0.f;
    #pragma unroll
    for (int hh = 0; hh < NHh; hh++) {
        int bh = b * NHh + hh;
        float inv = g_invs[(size_t)bh * Nn + i];
        const __nv_bfloat162* row = (const __nv_bfloat162*)(g_eh + ((size_t)bh * Nn + i) * Nn);
        __nv_bfloat162 v0 = row[tid * 2], v1 = row[tid * 2 + 1];
        a0 += __bfloat162float(v0.x) * inv;
        a1 += __bfloat162float(v0.y) * inv;
        a2 += __bfloat162float(v1.x) * inv;
        a3 += __bfloat162float(v1.y) * inv;
    }
    a0 *= (1.0f / NHh); a1 *= (1.0f / NHh); a2 *= (1.0f / NHh); a3 *= (1.0f / NHh);
    float hl = 0.0f;
    a0 = fmaxf(a0, 1e-10f); hl -= a0 * __logf(a0);
    a1 = fmaxf(a1, 1e-10f); hl -= a1 * __logf(a1);
    a2 = fmaxf(a2, 1e-10f); hl -= a2 * __logf(a2);
    a3 = fmaxf(a3, 1e-10f); hl -= a3 * __logf(a3);
    float H = blk_sum(hl);
    if (tid == 0) {
        float sig = 1.0f / (1.0f + __expf(H - 6.9314718055994531f));
        out_cert[bi] = fmaxf(cert[bi], sig);
    }
}

// ---------------- launch ----------------
extern "C" void kernel_launch(void* const* d_in, const int* in_sizes, int n_in,
                              void* d_out, int out_size) {
    const float* data  = (const float*)d_in[0];
    const float* tpos  = (const float*)d_in[1];
    const float* tquat = (const float*)d_in[2];
    const float* cert  = (const float*)d_in[3];
    const float* Wq = (const float*)d_in[4];  const float* bq = (const float*)d_in[5];
    const float* Wk = (const float*)d_in[6];  const float* bk = (const float*)d_in[7];
    const float* Wv = (const float*)d_in[8];  const float* bv = (const float*)d_in[9];
    const float* Wo = (const float*)d_in[10]; const float* bo = (const float*)d_in[11];
    float* out = (float*)d_out;

    // idempotent, host-side, capture-safe (no enqueue, no allocation)
    cudaFuncSetAttribute(attn_fused, cudaFuncAttributeMaxDynamicSharedMemorySize, ATTN_SMEM);
    cudaFuncSetAttribute(qkv_tc, cudaFuncAttributeMaxDynamicSharedMemorySize, GEMM_SMEM);
    cudaFuncSetAttribute(out_tc, cudaFuncAttributeMaxDynamicSharedMemorySize, GEMM_SMEM);

    prep_kernel<<<2560, 1024>>>(data, Wq, Wk, Wv, Wo, tpos, tquat);   // 1: splits + traj
    traj_norm_kernel<<<Nn, 256>>>();                                   // 2
    qkv_tc<<<dim3(8, 16, 3), 256, GEMM_SMEM>>>(bq, bk, bv);            // 3
    attn_fused<<<dim3(16, 32), 256, ATTN_SMEM>>>();                    // 4  <- ncu captures this
    entropy_kernel<<<Bb * Nn, 256>>>(cert, out + (size_t)Bb * Nn * Dd);// 5
    out_tc<<<dim3(8, 16, 2), 256, GEMM_SMEM>>>();                      // 6
    reduce_out<<<2048, 256>>>(bo, out);                                // 7
}

// round 15
// speedup vs baseline: 1.0495x; 1.0422x over previous
#include <cuda_runtime.h>
#include <cuda_bf16.h>
#include <math.h>
#include <stdint.h>

#define Bb  2
#define Tt  10
#define Nn  1024
#define Dd  1024
#define NHh 16
#define HDd 64
#define BT  (Bb*Tt)

// ---------------- scratch (static device globals; no allocation) ----------------
__device__ float g_traj[(size_t)Nn * Nn];

// bf16 hi/lo operand pairs
__device__ __nv_bfloat16 g_dh[(size_t)Bb * Nn * Dd],  g_dl[(size_t)Bb * Nn * Dd];
__device__ __nv_bfloat16 g_w3h[(size_t)3 * Dd * Dd],  g_w3l[(size_t)3 * Dd * Dd];
__device__ __nv_bfloat16 g_woh[(size_t)Dd * Dd],      g_wol[(size_t)Dd * Dd];
__device__ __nv_bfloat16 g_qh[(size_t)Bb * Nn * Dd],  g_ql[(size_t)Bb * Nn * Dd];   // Q/8
__device__ __nv_bfloat16 g_kh[(size_t)Bb * Nn * Dd],  g_kl[(size_t)Bb * Nn * Dd];
__device__ __nv_bfloat16 g_vh[(size_t)Bb * Nn * Dd],  g_vl[(size_t)Bb * Nn * Dd];
__device__ __nv_bfloat16 g_aoh[(size_t)Bb * Nn * Dd], g_aol[(size_t)Bb * Nn * Dd];
// unnormalized exp(scores) hi part (for entropy) + per-row 1/rowsum
__device__ __nv_bfloat16 g_eh[(size_t)Bb * NHh * Nn * Nn];
__device__ float g_invs[(size_t)Bb * NHh * Nn];
// split-K fp32 partials (out projection only)
__device__ float g_part[(size_t)2 * Bb * Nn * Dd];

// ================= HMMA helpers =================
__device__ __forceinline__ uint32_t smem_to_u32(const void* p) {
    uint32_t a;
    asm("{ .reg .u64 t; cvta.to.shared.u64 t, %1; cvt.u32.u64 %0, t; }" : "=r"(a) : "l"(p));
    return a;
}
__device__ __forceinline__ void cp16(uint32_t dst, const void* src) {
    asm volatile("cp.async.cg.shared.global [%0], [%1], 16;" :: "r"(dst), "l"(src));
}
#define CP_COMMIT() asm volatile("cp.async.commit_group;" ::: "memory")
#define CP_WAIT0()  asm volatile("cp.async.wait_group 0;" ::: "memory")

__device__ __forceinline__ void ldsm_x4(uint32_t* r, uint32_t addr) {
    asm volatile("ldmatrix.sync.aligned.m8n8.x4.shared.b16 {%0,%1,%2,%3}, [%4];"
                 : "=r"(r[0]), "=r"(r[1]), "=r"(r[2]), "=r"(r[3]) : "r"(addr));
}
__device__ __forceinline__ void ldsm_x4_t(uint32_t* r, uint32_t addr) {
    asm volatile("ldmatrix.sync.aligned.m8n8.x4.trans.shared.b16 {%0,%1,%2,%3}, [%4];"
                 : "=r"(r[0]), "=r"(r[1]), "=r"(r[2]), "=r"(r[3]) : "r"(addr));
}
// NON-volatile: lets ptxas interleave independent acc chains to hide HMMA latency.
__device__ __forceinline__ void mma_bf16(float* c, const uint32_t* a, uint32_t b0, uint32_t b1) {
    asm("mma.sync.aligned.m16n8k16.row.col.f32.bf16.bf16.f32 "
        "{%0,%1,%2,%3}, {%4,%5,%6,%7}, {%8,%9}, {%0,%1,%2,%3};"
        : "+f"(c[0]), "+f"(c[1]), "+f"(c[2]), "+f"(c[3])
        : "r"(a[0]), "r"(a[1]), "r"(a[2]), "r"(a[3]), "r"(b0), "r"(b1));
}
__device__ __forceinline__ __nv_bfloat162 split_hi2(float a, float b, float* ra, float* rb) {
    __nv_bfloat16 h0 = __float2bfloat16_rn(a), h1 = __float2bfloat16_rn(b);
    *ra = a - __bfloat162float(h0);
    *rb = b - __bfloat162float(h1);
    return __nv_bfloat162(h0, h1);
}
__device__ __forceinline__ uint32_t pack_bf162(__nv_bfloat16 a, __nv_bfloat16 b) {
    __nv_bfloat162 p(a, b);
    return *(uint32_t*)&p;
}

// ---------------- block reduction (256 threads) ----------------
__device__ __forceinline__ float blk_sum(float v) {
    __shared__ float red[8];
    #pragma unroll
    for (int o = 16; o > 0; o >>= 1) v += __shfl_xor_sync(0xffffffffu, v, o);
    int w = threadIdx.x >> 5, l = threadIdx.x & 31;
    if (l == 0) red[w] = v;
    __syncthreads();
    if (w == 0) {
        float r = (l < 8) ? red[l] : 0.0f;
        #pragma unroll
        for (int o = 4; o > 0; o >>= 1) r += __shfl_xor_sync(0xffffffffu, r, o);
        if (l == 0) red[0] = r;
    }
    __syncthreads();
    float out = red[0];
    __syncthreads();
    return out;
}

__device__ __forceinline__ float fast_sqrt(float x) {
    return x * rsqrtf(x + 1e-30f);
}

// ================= merged prep: bf16 splits (blocks 0..1535) + traj tiles (1536..2559) =================
__global__ __launch_bounds__(1024) void prep_kernel(const float* __restrict__ data,
                                                    const float* __restrict__ Wq, const float* __restrict__ Wk,
                                                    const float* __restrict__ Wv, const float* __restrict__ Wo,
                                                    const float* __restrict__ pos,
                                                    const float* __restrict__ quat) {
    __shared__ float Pi[3][BT][32], Pj[3][BT][32];
    __shared__ float Qi[4][BT][32], Qj[4][BT][32];
    int tid = threadIdx.x;

    if (blockIdx.x < 1536) {
        int oblk = (blockIdx.x << 2) | (tid >> 8);
        int ot = tid & 255;
        const float* src;
        __nv_bfloat16 *hi, *lo;
        int i;
        if (oblk < 2048) {
            src = data; hi = g_dh; lo = g_dl;
            i = oblk * 256 + ot;
        } else {
            int m = (oblk - 2048) >> 10;
            src = (m == 0) ? Wq : (m == 1) ? Wk : (m == 2) ? Wv : Wo;
            hi = (m < 3) ? g_w3h + (size_t)m * 1048576 : g_woh;
            lo = (m < 3) ? g_w3l + (size_t)m * 1048576 : g_wol;
            i = ((oblk - 2048) & 1023) * 256 + ot;
        }
        float4 x = ((const float4*)src)[i];
        float r0, r1, r2, r3;
        __nv_bfloat162 h01 = split_hi2(x.x, x.y, &r0, &r1);
        __nv_bfloat162 h23 = split_hi2(x.z, x.w, &r2, &r3);
        ((__nv_bfloat162*)hi)[i * 2 + 0] = h01;
        ((__nv_bfloat162*)hi)[i * 2 + 1] = h23;
        ((__nv_bfloat162*)lo)[i * 2 + 0] = __nv_bfloat162(__float2bfloat16_rn(r0), __float2bfloat16_rn(r1));
        ((__nv_bfloat162*)lo)[i * 2 + 1] = __nv_bfloat162(__float2bfloat16_rn(r2), __float2bfloat16_rn(r3));
        return;
    }

    int bIdx = blockIdx.x - 1536;
    int i0 = (bIdx >> 5) * 32, j0 = (bIdx & 31) * 32;

    for (int idx = tid; idx < BT * 32; idx += 1024) {
        int bt = idx >> 5, r = idx & 31;
        size_t pi = ((size_t)bt * Nn + i0 + r) * 3;
        size_t pj = ((size_t)bt * Nn + j0 + r) * 3;
        Pi[0][bt][r] = pos[pi + 0]; Pi[1][bt][r] = pos[pi + 1]; Pi[2][bt][r] = pos[pi + 2];
        Pj[0][bt][r] = pos[pj + 0]; Pj[1][bt][r] = pos[pj + 1]; Pj[2][bt][r] = pos[pj + 2];
        size_t qi = ((size_t)bt * Nn + i0 + r) * 4;
        size_t qj = ((size_t)bt * Nn + j0 + r) * 4;
        Qi[0][bt][r] = quat[qi + 0]; Qi[1][bt][r] = quat[qi + 1];
        Qi[2][bt][r] = quat[qi + 2]; Qi[3][bt][r] = quat[qi + 3];
        Qj[0][bt][r] = quat[qj + 0]; Qj[1][bt][r] = quat[qj + 1];
        Qj[2][bt][r] = quat[qj + 2]; Qj[3][bt][r] = quat[qj + 3];
    }
    __syncthreads();

    int ti = tid >> 5, tj = tid & 31;
    float spd = 0.0f, sqm = 0.0f, sqp = 0.0f;
    #pragma unroll
    for (int bt = 0; bt < BT; bt++) {
        float dx = Pi[0][bt][ti] - Pj[0][bt][tj];
        float dy = Pi[1][bt][ti] - Pj[1][bt][tj];
        float dz = Pi[2][bt][ti] - Pj[2][bt][tj];
        spd += fast_sqrt(dx * dx + dy * dy + dz * dz);
        float a0 = Qi[0][bt][ti], a1 = Qi[1][bt][ti], a2 = Qi[2][bt][ti], a3 = Qi[3][bt][ti];
        float b0 = Qj[0][bt][tj], b1 = Qj[1][bt][tj], b2 = Qj[2][bt][tj], b3 = Qj[3][bt][tj];
        float m0 = a0 - b0, m1 = a1 - b1, m2 = a2 - b2, m3 = a3 - b3;
        float p0 = a0 + b0, p1 = a1 + b1, p2 = a2 + b2, p3 = a3 + b3;
        sqm += fast_sqrt(m0 * m0 + m1 * m1 + m2 * m2 + m3 * m3);
        sqp += fast_sqrt(p0 * p0 + p1 * p1 + p2 * p2 + p3 * p3);
    }
    float pd = spd * (1.0f / BT);
    float qd = fminf(sqm, sqp) * (1.0f / BT);
    g_traj[(size_t)(i0 + ti) * Nn + (j0 + tj)] = __expf(-(pd + qd));
}

// ---------------- row-normalize traj (folds in 0.5 bias scale) ----------------
__global__ __launch_bounds__(256) void traj_norm_kernel() {
    float* row = g_traj + (size_t)blockIdx.x * Nn;
    float4 v = ((const float4*)row)[threadIdx.x];
    float s = blk_sum(v.x + v.y + v.z + v.w);
    float sc = 0.5f / s;
    v.x *= sc; v.y *= sc; v.z *= sc; v.w *= sc;
    ((float4*)row)[threadIdx.x] = v;
}

// ================= HMMA GEMM core: 128x128 tile, K-chunk 32, 2-stage single-sync =================
#define GSTG       40960
#define GMAT       10240
#define GEMM_SMEM  (2 * GSTG)

__device__ __forceinline__ void hmma_gemm_body(const __nv_bfloat16* __restrict__ Ah,
                                               const __nv_bfloat16* __restrict__ Al,
                                               const __nv_bfloat16* __restrict__ Wh,
                                               const __nv_bfloat16* __restrict__ Wl,
                                               int k0, int nchunks,
                                               const float* __restrict__ bias,
                                               float scale, int mode,
                                               float* __restrict__ Cpart,
                                               __nv_bfloat16* __restrict__ Chi,
                                               __nv_bfloat16* __restrict__ Clo) {
    extern __shared__ __align__(16) char gsm[];
    uint32_t ub = smem_to_u32(gsm);
    int tid = threadIdx.x, lane = tid & 31, wid = tid >> 5;
    int wm = wid & 3, wn = wid >> 2;
    int m0 = blockIdx.y << 7, n0 = blockIdx.x << 7;

    const __nv_bfloat16* srcs[4] = {
        Ah + (size_t)m0 * Dd + k0, Al + (size_t)m0 * Dd + k0,
        Wh + (size_t)n0 * Dd + k0, Wl + (size_t)n0 * Dd + k0 };

    float acc[2][8][4];
    #pragma unroll
    for (int i = 0; i < 2; i++)
        #pragma unroll
        for (int j = 0; j < 8; j++)
            #pragma unroll
            for (int k = 0; k < 4; k++) acc[i][j][k] = 0.0f;

    #pragma unroll
    for (int s = 0; s < 8; s++) {
        int idx = tid + (s << 8);
        int mat = idx >> 9, row = (idx >> 2) & 127, seg = idx & 3;
        cp16(ub + mat * GMAT + row * 80 + seg * 16,
             srcs[mat] + (size_t)row * Dd + seg * 8);
    }
    CP_COMMIT();

    int rsel = lane & 15;
    int cselb = ((lane >> 4) << 4);

    for (int c = 0; c < nchunks; c++) {
        int st = c & 1;
        CP_WAIT0();
        __syncthreads();
        if (c + 1 < nchunks) {
            int nst = st ^ 1, kc = (c + 1) << 5;
            #pragma unroll
            for (int s = 0; s < 8; s++) {
                int idx = tid + (s << 8);
                int mat = idx >> 9, row = (idx >> 2) & 127, seg = idx & 3;
                cp16(ub + nst * GSTG + mat * GMAT + row * 80 + seg * 16,
                     srcs[mat] + (size_t)row * Dd + kc + seg * 8);
            }
            CP_COMMIT();
        }

        uint32_t base = ub + st * GSTG;
        #pragma unroll
        for (int kk = 0; kk < 2; kk++) {
            uint32_t ah[2][4], al[2][4];
            #pragma unroll
            for (int mb = 0; mb < 2; mb++) {
                int row = wm * 32 + mb * 16 + rsel;
                ldsm_x4(ah[mb], base + row * 80 + kk * 32 + cselb);
                ldsm_x4(al[mb], base + GMAT + row * 80 + kk * 32 + cselb);
            }
            #pragma unroll
            for (int np = 0; np < 4; np++) {
                uint32_t bh[4], bl[4];
                int row = wn * 64 + np * 16 + rsel;
                ldsm_x4(bh, base + 2 * GMAT + row * 80 + kk * 32 + cselb);
                ldsm_x4(bl, base + 3 * GMAT + row * 80 + kk * 32 + cselb);
                #pragma unroll
                for (int mb = 0; mb < 2; mb++) {
                    mma_bf16(acc[mb][2 * np + 0], ah[mb], bh[0], bh[2]);
                    mma_bf16(acc[mb][2 * np + 1], ah[mb], bh[1], bh[3]);
                    mma_bf16(acc[mb][2 * np + 0], ah[mb], bl[0], bl[2]);
                    mma_bf16(acc[mb][2 * np + 1], ah[mb], bl[1], bl[3]);
                    mma_bf16(acc[mb][2 * np + 0], al[mb], bh[0], bh[2]);
                    mma_bf16(acc[mb][2 * np + 1], al[mb], bh[1], bh[3]);
                }
            }
        }
    }

    #pragma unroll
    for (int mb = 0; mb < 2; mb++) {
        int r0 = m0 + wm * 32 + mb * 16 + (lane >> 2);
        #pragma unroll
        for (int nb = 0; nb < 8; nb++) {
            int col = n0 + wn * 64 + nb * 8 + ((lane & 3) << 1);
            if (mode == 2) {
                *(float2*)(Cpart + (size_t)r0 * Dd + col)       = make_float2(acc[mb][nb][0], acc[mb][nb][1]);
                *(float2*)(Cpart + (size_t)(r0 + 8) * Dd + col) = make_float2(acc[mb][nb][2], acc[mb][nb][3]);
            } else {
                float b0 = bias[col], b1 = bias[col + 1];
                float x0 = (acc[mb][nb][0] + b0) * scale, x1 = (acc[mb][nb][1] + b1) * scale;
                float x2 = (acc[mb][nb][2] + b0) * scale, x3 = (acc[mb][nb][3] + b1) * scale;
                float l0, l1, l2, l3;
                __nv_bfloat162 h01 = split_hi2(x0, x1, &l0, &l1);
                __nv_bfloat162 h23 = split_hi2(x2, x3, &l2, &l3);
                *(__nv_bfloat162*)(Chi + (size_t)r0 * Dd + col)       = h01;
                *(__nv_bfloat162*)(Chi + (size_t)(r0 + 8) * Dd + col) = h23;
                *(__nv_bfloat162*)(Clo + (size_t)r0 * Dd + col) =
                    __nv_bfloat162(__float2bfloat16_rn(l0), __float2bfloat16_rn(l1));
                *(__nv_bfloat162*)(Clo + (size_t)(r0 + 8) * Dd + col) =
                    __nv_bfloat162(__float2bfloat16_rn(l2), __float2bfloat16_rn(l3));
            }
        }
    }
}

__global__ __launch_bounds__(256, 2) void qkv_tc(const float* __restrict__ bq,
                                                 const float* __restrict__ bk,
                                                 const float* __restrict__ bv) {
    int z = blockIdx.z;
    const __nv_bfloat16* Wh = g_w3h + (size_t)z * 1048576;
    const __nv_bfloat16* Wl = g_w3l + (size_t)z * 1048576;
    const float* bias = (z == 0) ? bq : (z == 1) ? bk : bv;
    __nv_bfloat16* Chi = (z == 0) ? g_qh : (z == 1) ? g_kh : g_vh;
    __nv_bfloat16* Clo = (z == 0) ? g_ql : (z == 1) ? g_kl : g_vl;
    float scale = (z == 0) ? 0.125f : 1.0f;
    hmma_gemm_body(g_dh, g_dl, Wh, Wl, 0, 32, bias, scale, 0, nullptr, Chi, Clo);
}

__global__ __launch_bounds__(256, 2) void out_tc() {
    int kh = blockIdx.z;
    float* Cpart = g_part + (size_t)kh * 2097152;
    hmma_gemm_body(g_aoh, g_aol, g_woh, g_wol, kh * 512, 16, nullptr, 1.0f, 2, Cpart, nullptr, nullptr);
}

__global__ __launch_bounds__(256) void reduce_out(const float* __restrict__ bo,
                                                  float* __restrict__ out) {
    size_t p = (size_t)blockIdx.x * 256 + threadIdx.x;
    const float4* P = (const float4*)g_part;
    float4 a = P[p];
    float4 b = P[524288 + p];
    float4 bi = *(const float4*)(bo + ((p & 255) << 2));
    ((float4*)out)[p] = make_float4(a.x + b.x + bi.x, a.y + b.y + bi.y,
                                    a.z + b.z + bi.z, a.w + b.w + bi.w);
}

// ================= fused attention: scores+traj -> exp -> PV, flash-style =================
// 2 CTAs/SM. Q fragments hoisted into registers (loop-invariant): removes 8 ldsm/warp/chunk,
// cutting scores-phase L1 traffic by 33% (L1 was the top pipe at 59.7%).
#define AQH 0
#define AQL 9216
#define ASTG(st) (18432 + (st) * 18432)
#define ARS 55296
#define AIV 55808
#define ATTN_SMEM 56064

__global__ __launch_bounds__(256, 2) void attn_fused() {
    extern __shared__ __align__(16) char sm[];
    uint32_t ub = smem_to_u32(sm);
    int tid = threadIdx.x, lane = tid & 31, wid = tid >> 5;
    int wm = wid & 3, wn = wid >> 2;
    int g = lane >> 2, t = lane & 3;
    int rsel = lane & 15, csel = (lane >> 4) << 3;
    int bh = blockIdx.y, b = bh >> 4, h = bh & 15;
    int i0 = blockIdx.x << 6;

    const __nv_bfloat16* kvsrc[4] = { g_kh, g_kl, g_vh, g_vl };
    #pragma unroll
    for (int s = 0; s < 4; s++) {
        int idx = tid + (s << 8);
        int mat = idx >> 9, row = (idx >> 3) & 63, seg = idx & 7;
        const __nv_bfloat16* src = (mat == 0 ? g_qh : g_ql) +
            ((size_t)(b * Nn + i0 + row)) * Dd + h * HDd + seg * 8;
        cp16(ub + (mat ? AQL : AQH) + (row * 72 + seg * 8) * 2, src);
    }
    #pragma unroll
    for (int s = 0; s < 4; s++) {
        int idx = tid + (s << 8);
        int mat = idx >> 8, row = (idx >> 3) & 31, seg = idx & 7;
        const __nv_bfloat16* src = kvsrc[mat] + ((size_t)(b * Nn + row)) * Dd + h * HDd + seg * 8;
        cp16(ub + ASTG(0) + mat * 4608 + (row * 72 + seg * 8) * 2, src);
    }
    CP_COMMIT();

    float pacc[8][4];
    #pragma unroll
    for (int i = 0; i < 8; i++)
        #pragma unroll
        for (int j = 0; j < 4; j++) pacc[i][j] = 0.0f;
    float rs0 = 0.0f, rs1 = 0.0f;

    int i_r0 = i0 + wm * 16 + g;

    // wait for Q + KV0, then hoist Q fragments into registers (loop-invariant)
    CP_WAIT0();
    __syncthreads();
    uint32_t qh_r[4][4], ql_r[4][4];
    #pragma unroll
    for (int k = 0; k < 4; k++) {
        uint32_t qaddr = (uint32_t)(((wm * 16 + rsel) * 72 + k * 16 + csel) * 2);
        ldsm_x4(qh_r[k], ub + AQH + qaddr);
        ldsm_x4(ql_r[k], ub + AQL + qaddr);
    }

    for (int c = 0; c < 32; c++) {
        int st = c & 1;
        if (c > 0) {
            CP_WAIT0();
            __syncthreads();
        }
        if (c < 31) {
            int jc1 = (c + 1) << 5, nst = st ^ 1;
            #pragma unroll
            for (int s = 0; s < 4; s++) {
                int idx = tid + (s << 8);
                int mat = idx >> 8, row = (idx >> 3) & 31, seg = idx & 7;
                const __nv_bfloat16* src = kvsrc[mat] +
                    ((size_t)(b * Nn + jc1 + row)) * Dd + h * HDd + seg * 8;
                cp16(ub + ASTG(nst) + mat * 4608 + (row * 72 + seg * 8) * 2, src);
            }
            CP_COMMIT();
        }

        uint32_t kbase = ub + ASTG(st);
        int jc = c << 5;

        float sacc0[4] = {0.f, 0.f, 0.f, 0.f};
        float sacc1[4] = {0.f, 0.f, 0.f, 0.f};
        #pragma unroll
        for (int k = 0; k < 4; k++) {
            uint32_t kh[4], kl[4];
            uint32_t kaddr = (uint32_t)(((wn * 16 + rsel) * 72 + k * 16 + csel) * 2);
            ldsm_x4(kh, kbase + kaddr);
            ldsm_x4(kl, kbase + 4608 + kaddr);
            mma_bf16(sacc0, qh_r[k], kh[0], kh[2]); mma_bf16(sacc1, qh_r[k], kh[1], kh[3]);
            mma_bf16(sacc0, qh_r[k], kl[0], kl[2]); mma_bf16(sacc1, qh_r[k], kl[1], kl[3]);
            mma_bf16(sacc0, ql_r[k], kh[0], kh[2]); mma_bf16(sacc1, ql_r[k], kh[1], kh[3]);
        }

        uint32_t ah[4], al[4];
        {
            float* sa = sacc0;
            #pragma unroll
            for (int nt = 0; nt < 2; nt++) {
                int jj = jc + wn * 16 + nt * 8 + 2 * t;
                float2 tv0 = *(const float2*)(g_traj + (size_t)i_r0 * Nn + jj);
                float2 tv1 = *(const float2*)(g_traj + (size_t)(i_r0 + 8) * Nn + jj);
                float e0 = __expf(sa[0] + tv0.x), e1 = __expf(sa[1] + tv0.y);
                float e2 = __expf(sa[2] + tv1.x), e3 = __expf(sa[3] + tv1.y);
                rs0 += e0 + e1; rs1 += e2 + e3;
                __nv_bfloat16 h0 = __float2bfloat16_rn(e0), h1 = __float2bfloat16_rn(e1);
                __nv_bfloat16 h2 = __float2bfloat16_rn(e2), h3 = __float2bfloat16_rn(e3);
                float l0 = e0 - __bfloat162float(h0), l1 = e1 - __bfloat162float(h1);
                float l2 = e2 - __bfloat162float(h2), l3 = e3 - __bfloat162float(h3);
                *(__nv_bfloat162*)(g_eh + ((size_t)bh * Nn + i_r0) * Nn + jj)     = __nv_bfloat162(h0, h1);
                *(__nv_bfloat162*)(g_eh + ((size_t)bh * Nn + i_r0 + 8) * Nn + jj) = __nv_bfloat162(h2, h3);
                ah[nt * 2 + 0] = pack_bf162(h0, h1);
                ah[nt * 2 + 1] = pack_bf162(h2, h3);
                al[nt * 2 + 0] = pack_bf162(__float2bfloat16_rn(l0), __float2bfloat16_rn(l1));
                al[nt * 2 + 1] = pack_bf162(__float2bfloat16_rn(l2), __float2bfloat16_rn(l3));
                sa = sacc1;
            }
        }

        #pragma unroll
        for (int db = 0; db < 4; db++) {
            uint32_t vh[4], vl[4];
            uint32_t vaddr = (uint32_t)(((wn * 16 + rsel) * 72 + db * 16 + csel) * 2);
            ldsm_x4_t(vh, kbase + 9216 + vaddr);
            ldsm_x4_t(vl, kbase + 13824 + vaddr);
            mma_bf16(pacc[2 * db + 0], ah, vh[0], vh[1]); mma_bf16(pacc[2 * db + 1], ah, vh[2], vh[3]);
            mma_bf16(pacc[2 * db + 0], al, vh[0], vh[1]); mma_bf16(pacc[2 * db + 1], al, vh[2], vh[3]);
            mma_bf16(pacc[2 * db + 0], ah, vl[0], vl[1]); mma_bf16(pacc[2 * db + 1], ah, vl[2], vl[3]);
        }
    }

    rs0 += __shfl_xor_sync(0xffffffffu, rs0, 1);
    rs0 += __shfl_xor_sync(0xffffffffu, rs0, 2);
    rs1 += __shfl_xor_sync(0xffffffffu, rs1, 1);
    rs1 += __shfl_xor_sync(0xffffffffu, rs1, 2);
    float* s_rs = (float*)(sm + ARS);
    float* s_iv = (float*)(sm + AIV);
    if (t == 0) {
        s_rs[wn * 64 + wm * 16 + g]     = rs0;
        s_rs[wn * 64 + wm * 16 + g + 8] = rs1;
    }
    __syncthreads();
    if (tid < 64) {
        float s = s_rs[tid] + s_rs[64 + tid];
        float inv = 1.0f / s;
        s_iv[tid] = inv;
        g_invs[(size_t)bh * Nn + i0 + tid] = inv;
    }
    __syncthreads();

    float* red = (float*)(sm + ASTG(0)) + wm * 1056;
    if (wn == 0) {
        #pragma unroll
        for (int nt = 0; nt < 8; nt++) {
            int col = nt * 8 + 2 * t;
            red[g * 66 + col]           = pacc[nt][0];
            red[g * 66 + col + 1]       = pacc[nt][1];
            red[(g + 8) * 66 + col]     = pacc[nt][2];
            red[(g + 8) * 66 + col + 1] = pacc[nt][3];
        }
    }
    __syncthreads();
    if (wn == 1) {
        float inv0 = s_iv[wm * 16 + g], inv1 = s_iv[wm * 16 + g + 8];
        #pragma unroll
        for (int nt = 0; nt < 8; nt++) {
            int col = nt * 8 + 2 * t;
            float x0 = (pacc[nt][0] + red[g * 66 + col])           * inv0;
            float x1 = (pacc[nt][1] + red[g * 66 + col + 1])       * inv0;
            float x2 = (pacc[nt][2] + red[(g + 8) * 66 + col])     * inv1;
            float x3 = (pacc[nt][3] + red[(g + 8) * 66 + col + 1]) * inv1;
            float l0, l1, l2, l3;
            __nv_bfloat162 h01 = split_hi2(x0, x1, &l0, &l1);
            __nv_bfloat162 h23 = split_hi2(x2, x3, &l2, &l3);
            size_t o0 = ((size_t)b * Nn + i_r0) * Dd + h * HDd + col;
            size_t o1 = ((size_t)b * Nn + i_r0 + 8) * Dd + h * HDd + col;
            *(__nv_bfloat162*)(g_aoh + o0) = h01;
            *(__nv_bfloat162*)(g_aoh + o1) = h23;
            *(__nv_bfloat162*)(g_aol + o0) = __nv_bfloat162(__float2bfloat16_rn(l0), __float2bfloat16_rn(l1));
            *(__nv_bfloat162*)(g_aol + o1) = __nv_bfloat162(__float2bfloat16_rn(l2), __float2bfloat16_rn(l3));
        }
    }
}

// ---------------- entropy + certainty ----------------
__global__ __launch_bounds__(256) void entropy_kernel(const float* __restrict__ cert,
                                                      float* __restrict__ out_cert) {
    int bi = blockIdx.x;
    int b = bi >> 10, i = bi & 1023;
    int tid = threadIdx.x;

    float a0 = 0.f, a1 = 0.f, a2 = 0.f, a3 = 0.f;
    #pragma unroll
    for (int hh = 0; hh < NHh; hh++) {
        int bh = b * NHh + hh;
        float inv = g_invs[(size_t)bh * Nn + i];
        const __nv_bfloat162* row = (const __nv_bfloat162*)(g_eh + ((size_t)bh * Nn + i) * Nn);
        __nv_bfloat162 v0 = row[tid * 2], v1 = row[tid * 2 + 1];
        a0 += __bfloat162float(v0.x) * inv;
        a1 += __bfloat162float(v0.y) * inv;
        a2 += __bfloat162float(v1.x) * inv;
        a3 += __bfloat162float(v1.y) * inv;
    }
    a0 *= (1.0f / NHh); a1 *= (1.0f / NHh); a2 *= (1.0f / NHh); a3 *= (1.0f / NHh);
    float hl = 0.0f;
    a0 = fmaxf(a0, 1e-10f); hl -= a0 * __logf(a0);
    a1 = fmaxf(a1, 1e-10f); hl -= a1 * __logf(a1);
    a2 = fmaxf(a2, 1e-10f); hl -= a2 * __logf(a2);
    a3 = fmaxf(a3, 1e-10f); hl -= a3 * __logf(a3);
    float H = blk_sum(hl);
    if (tid == 0) {
        float sig = 1.0f / (1.0f + __expf(H - 6.9314718055994531f));
        out_cert[bi] = fmaxf(cert[bi], sig);
    }
}

// ---------------- launch ----------------
extern "C" void kernel_launch(void* const* d_in, const int* in_sizes, int n_in,
                              void* d_out, int out_size) {
    const float* data  = (const float*)d_in[0];
    const float* tpos  = (const float*)d_in[1];
    const float* tquat = (const float*)d_in[2];
    const float* cert  = (const float*)d_in[3];
    const float* Wq = (const float*)d_in[4];  const float* bq = (const float*)d_in[5];
    const float* Wk = (const float*)d_in[6];  const float* bk = (const float*)d_in[7];
    const float* Wv = (const float*)d_in[8];  const float* bv = (const float*)d_in[9];
    const float* Wo = (const float*)d_in[10]; const float* bo = (const float*)d_in[11];
    float* out = (float*)d_out;

    // idempotent, host-side, capture-safe (no enqueue, no allocation)
    cudaFuncSetAttribute(attn_fused, cudaFuncAttributeMaxDynamicSharedMemorySize, ATTN_SMEM);
    cudaFuncSetAttribute(qkv_tc, cudaFuncAttributeMaxDynamicSharedMemorySize, GEMM_SMEM);
    cudaFuncSetAttribute(out_tc, cudaFuncAttributeMaxDynamicSharedMemorySize, GEMM_SMEM);

    prep_kernel<<<2560, 1024>>>(data, Wq, Wk, Wv, Wo, tpos, tquat);   // 1
    traj_norm_kernel<<<Nn, 256>>>();                                   // 2
    qkv_tc<<<dim3(8, 16, 3), 256, GEMM_SMEM>>>(bq, bk, bv);            // 3
    attn_fused<<<dim3(16, 32), 256, ATTN_SMEM>>>();                    // 4  <- ncu captures this
    entropy_kernel<<<Bb * Nn, 256>>>(cert, out + (size_t)Bb * Nn * Dd);// 5
    out_tc<<<dim3(8, 16, 2), 256, GEMM_SMEM>>>();                      // 6
    reduce_out<<<2048, 256>>>(bo, out);                                // 7
}